// round 1
// baseline (speedup 1.0000x reference)
#include <cuda_runtime.h>

// Problem dims (fixed by the dataset)
#define BQ   256     // batch
#define NTOK 196     // tokens w/o cls
#define NTOT 197
#define DIM  768
#define DTXT 512
#define TTOT (BQ*NTOK)   // 50176

// ---------------- scratch (device globals; no allocations allowed) -------------
__device__ float g_attn[(size_t)BQ*NTOK*NTOK];   // 39.3 MB  scores / softmax(A)
__device__ float g_buf1[(size_t)TTOT*DIM];       // 154 MB   msg
__device__ float g_buf2[(size_t)TTOT*DIM];       // 154 MB   h = gelu(msg@w1+b1)
__device__ float g_txt [(size_t)BQ*DIM];         // gelu(text@w1_txt+b1)
__device__ float g_tq  [(size_t)BQ*DIM];         // tq (post-LN)

__device__ __forceinline__ float gelu_exact(float x) {
    // x * Phi(x), Phi = standard normal CDF == 0.5*(1+erf(x/sqrt(2)))
    return x * normcdff(x);
}

// =====================================================================
// Generic tiled GEMM:  C = alpha * A(MxK) * op(B) + epilogue
//   BT=false : B is K x N row-major            (NN)
//   BT=true  : B is N x K row-major (B^T used) (NT)
// MODE 0: C = alpha*acc                      (scores, msg)
// MODE 1: C = gelu(acc + bias)               (mlp1, text1)
// MODE 2: C = acc + bias                     (text2)
// MODE 3: out[remap] = resid[remap] + g*(acc+bias)   (mlp2 + residual into d_out)
// 64x64 tile, BK=16, 256 threads, 4x4 microtile, float4 smem paths.
// =====================================================================
template<int MODE, bool BT>
__launch_bounds__(256)
__global__ void gemm_kernel(const float* __restrict__ A, long aBS, int lda,
                            const float* __restrict__ B, long bBS, int ldb,
                            float* __restrict__ C, long cBS, int ldc,
                            int M, int N, int K, float alpha,
                            const float* __restrict__ bias,
                            const float* __restrict__ resid,
                            const float* __restrict__ gscale)
{
    const int BM = 64, BN = 64, BK = 16;
    __shared__ float Ast[BK][BM + 4];                       // A^T tile: [k][m]
    __shared__ float Bst[BK][BT ? (BM + 4) : BN];           // [k][n]

    const int tid = threadIdx.x;
    const int tx  = tid & 15;        // 0..15 -> n microtile
    const int ty  = tid >> 4;        // 0..15 -> m microtile
    const int m0  = blockIdx.y * BM;
    const int n0  = blockIdx.x * BN;

    const float* Ab = A + (long)blockIdx.z * aBS;
    const float* Bb = B + (long)blockIdx.z * bBS;

    float acc[4][4] = {};

    const int aRow = tid >> 2;            // 0..63
    const int aCol = (tid & 3) * 4;       // 0,4,8,12

    for (int k0 = 0; k0 < K; k0 += BK) {
        // ---- load A tile, transposed into Ast[k][m] ----
        {
            float4 v = make_float4(0.f, 0.f, 0.f, 0.f);
            int gr = m0 + aRow;
            if (gr < M) {
                int gc = k0 + aCol;
                if (gc + 3 < K) {
                    v = *reinterpret_cast<const float4*>(Ab + (long)gr * lda + gc);
                } else {
                    float t0 = (gc + 0 < K) ? Ab[(long)gr * lda + gc + 0] : 0.f;
                    float t1 = (gc + 1 < K) ? Ab[(long)gr * lda + gc + 1] : 0.f;
                    float t2 = (gc + 2 < K) ? Ab[(long)gr * lda + gc + 2] : 0.f;
                    float t3 = (gc + 3 < K) ? Ab[(long)gr * lda + gc + 3] : 0.f;
                    v = make_float4(t0, t1, t2, t3);
                }
            }
            Ast[aCol + 0][aRow] = v.x;
            Ast[aCol + 1][aRow] = v.y;
            Ast[aCol + 2][aRow] = v.z;
            Ast[aCol + 3][aRow] = v.w;
        }
        // ---- load B tile ----
        if (BT) {
            // B is N x K row-major; tile rows are n, cols are k -> transpose in
            float4 v = make_float4(0.f, 0.f, 0.f, 0.f);
            int gr = n0 + aRow;
            if (gr < N) {
                int gc = k0 + aCol;
                if (gc + 3 < K) {
                    v = *reinterpret_cast<const float4*>(Bb + (long)gr * ldb + gc);
                } else {
                    float t0 = (gc + 0 < K) ? Bb[(long)gr * ldb + gc + 0] : 0.f;
                    float t1 = (gc + 1 < K) ? Bb[(long)gr * ldb + gc + 1] : 0.f;
                    float t2 = (gc + 2 < K) ? Bb[(long)gr * ldb + gc + 2] : 0.f;
                    float t3 = (gc + 3 < K) ? Bb[(long)gr * ldb + gc + 3] : 0.f;
                    v = make_float4(t0, t1, t2, t3);
                }
            }
            Bst[aCol + 0][aRow] = v.x;
            Bst[aCol + 1][aRow] = v.y;
            Bst[aCol + 2][aRow] = v.z;
            Bst[aCol + 3][aRow] = v.w;
        } else {
            // B is K x N row-major
            int br = tid >> 4;             // 0..15  (k)
            int bc = (tid & 15) * 4;       // 0..60  (n)
            float4 v = make_float4(0.f, 0.f, 0.f, 0.f);
            int gk = k0 + br;
            int gn = n0 + bc;
            if (gk < K && gn < N) {
                if (gn + 3 < N) {
                    v = *reinterpret_cast<const float4*>(Bb + (long)gk * ldb + gn);
                } else {
                    float t0 = (gn + 0 < N) ? Bb[(long)gk * ldb + gn + 0] : 0.f;
                    float t1 = (gn + 1 < N) ? Bb[(long)gk * ldb + gn + 1] : 0.f;
                    float t2 = (gn + 2 < N) ? Bb[(long)gk * ldb + gn + 2] : 0.f;
                    float t3 = (gn + 3 < N) ? Bb[(long)gk * ldb + gn + 3] : 0.f;
                    v = make_float4(t0, t1, t2, t3);
                }
            }
            *reinterpret_cast<float4*>(&Bst[br][bc]) = v;
        }
        __syncthreads();

        #pragma unroll
        for (int k = 0; k < BK; k++) {
            float4 av = *reinterpret_cast<const float4*>(&Ast[k][ty * 4]);
            float4 bv = *reinterpret_cast<const float4*>(&Bst[k][tx * 4]);
            acc[0][0] += av.x * bv.x; acc[0][1] += av.x * bv.y;
            acc[0][2] += av.x * bv.z; acc[0][3] += av.x * bv.w;
            acc[1][0] += av.y * bv.x; acc[1][1] += av.y * bv.y;
            acc[1][2] += av.y * bv.z; acc[1][3] += av.y * bv.w;
            acc[2][0] += av.z * bv.x; acc[2][1] += av.z * bv.y;
            acc[2][2] += av.z * bv.z; acc[2][3] += av.z * bv.w;
            acc[3][0] += av.w * bv.x; acc[3][1] += av.w * bv.y;
            acc[3][2] += av.w * bv.z; acc[3][3] += av.w * bv.w;
        }
        __syncthreads();
    }

    float g = (MODE == 3) ? gscale[0] : 0.f;

    #pragma unroll
    for (int i = 0; i < 4; i++) {
        int m = m0 + ty * 4 + i;
        if (m >= M) continue;
        #pragma unroll
        for (int j = 0; j < 4; j++) {
            int n = n0 + tx * 4 + j;
            if (n >= N) continue;
            float v = acc[i][j];
            if (MODE == 0) v *= alpha;
            if (MODE >= 1) v += bias[n];
            if (MODE == 1) v = gelu_exact(v);
            if (MODE == 3) {
                int b = m / NTOK;
                int r = m - b * NTOK;
                long off = ((long)b * NTOT + 1 + r) * DIM + n;
                C[off] = resid[off] + g * v;
            } else {
                C[(long)blockIdx.z * cBS + (long)m * ldc + n] = v;
            }
        }
    }
}

// ---------------- softmax over rows of g_attn (one warp per row) -------------
__global__ void softmax_kernel(float* __restrict__ S)
{
    int warp = (blockIdx.x * blockDim.x + threadIdx.x) >> 5;
    int lane = threadIdx.x & 31;
    if (warp >= (int)(BQ * NTOK)) return;
    float* p = S + (long)warp * NTOK;

    float v[7];
    float mx = -3.0e38f;
    #pragma unroll
    for (int it = 0; it < 7; it++) {
        int j = lane + it * 32;
        v[it] = (j < NTOK) ? p[j] : -3.0e38f;
        mx = fmaxf(mx, v[it]);
    }
    #pragma unroll
    for (int o = 16; o; o >>= 1) mx = fmaxf(mx, __shfl_xor_sync(0xffffffffu, mx, o));

    float s = 0.f;
    #pragma unroll
    for (int it = 0; it < 7; it++) {
        int j = lane + it * 32;
        if (j < NTOK) { v[it] = expf(v[it] - mx); s += v[it]; } else v[it] = 0.f;
    }
    #pragma unroll
    for (int o = 16; o; o >>= 1) s += __shfl_xor_sync(0xffffffffu, s, o);
    float inv = 1.f / s;
    #pragma unroll
    for (int it = 0; it < 7; it++) {
        int j = lane + it * 32;
        if (j < NTOK) p[j] = v[it] * inv;
    }
}

// ---------------- layernorm rows of g_tq in place ----------------------------
__global__ void layernorm_kernel(float* __restrict__ X,
                                 const float* __restrict__ w,
                                 const float* __restrict__ b)
{
    int row = blockIdx.x;
    float* p = X + (long)row * DIM;
    float s = 0.f, sq = 0.f;
    for (int j = threadIdx.x; j < DIM; j += blockDim.x) {
        float x = p[j]; s += x; sq += x * x;
    }
    __shared__ float rs[32], rq[32];
    int lane = threadIdx.x & 31, wid = threadIdx.x >> 5;
    #pragma unroll
    for (int o = 16; o; o >>= 1) {
        s  += __shfl_xor_sync(0xffffffffu, s, o);
        sq += __shfl_xor_sync(0xffffffffu, sq, o);
    }
    if (lane == 0) { rs[wid] = s; rq[wid] = sq; }
    __syncthreads();
    int nw = blockDim.x >> 5;
    if (wid == 0) {
        float a = (lane < nw) ? rs[lane] : 0.f;
        float c = (lane < nw) ? rq[lane] : 0.f;
        #pragma unroll
        for (int o = 16; o; o >>= 1) {
            a += __shfl_xor_sync(0xffffffffu, a, o);
            c += __shfl_xor_sync(0xffffffffu, c, o);
        }
        if (lane == 0) { rs[0] = a; rq[0] = c; }
    }
    __syncthreads();
    float mu  = rs[0] / DIM;
    float var = rq[0] / DIM - mu * mu;
    float rstd = rsqrtf(var + 1e-5f);
    for (int j = threadIdx.x; j < DIM; j += blockDim.x)
        p[j] = (p[j] - mu) * rstd * w[j] + b[j];
}

// ----- gating: out_row *= (1 + gamma * sigmoid(dot(out_row, tq_b)))  (in place)
__global__ void mask_refine_kernel(float* __restrict__ out,
                                   const float* __restrict__ tq,
                                   const float* __restrict__ gamma)
{
    int warp = (blockIdx.x * blockDim.x + threadIdx.x) >> 5;
    int lane = threadIdx.x & 31;
    if (warp >= (int)TTOT) return;
    int b = warp / NTOK;
    int r = warp - b * NTOK;
    float* p = out + ((long)b * NTOT + 1 + r) * DIM;
    const float* t = tq + (long)b * DIM;
    float d = 0.f;
    for (int j = lane; j < DIM; j += 32) d += p[j] * t[j];
    #pragma unroll
    for (int o = 16; o; o >>= 1) d += __shfl_xor_sync(0xffffffffu, d, o);
    float m  = 1.f / (1.f + expf(-d));
    float sc = 1.f + gamma[0] * m;
    for (int j = lane; j < DIM; j += 32) p[j] *= sc;
}

// ---------------- cls passthrough --------------------------------------------
__global__ void copy_cls_kernel(const float* __restrict__ img, float* __restrict__ out)
{
    int b = blockIdx.x;
    long base = (long)b * NTOT * DIM;
    for (int j = threadIdx.x; j < DIM; j += blockDim.x)
        out[base + j] = img[base + j];
}

// =====================================================================
extern "C" void kernel_launch(void* const* d_in, const int* in_sizes, int n_in,
                              void* d_out, int out_size)
{
    const float* img       = (const float*)d_in[0];
    const float* text      = (const float*)d_in[1];
    const float* w1_msg    = (const float*)d_in[2];
    const float* b1_msg    = (const float*)d_in[3];
    const float* w2_msg    = (const float*)d_in[4];
    const float* b2_msg    = (const float*)d_in[5];
    const float* gamma_gcn = (const float*)d_in[6];
    const float* w1_txt    = (const float*)d_in[7];
    const float* b1_txt    = (const float*)d_in[8];
    const float* w2_txt    = (const float*)d_in[9];
    const float* b2_txt    = (const float*)d_in[10];
    const float* ln_w      = (const float*)d_in[11];
    const float* ln_b      = (const float*)d_in[12];
    const float* gamma     = (const float*)d_in[13];
    float* out = (float*)d_out;

    float *attn, *buf1, *buf2, *txt, *tq;
    cudaGetSymbolAddress((void**)&attn, g_attn);
    cudaGetSymbolAddress((void**)&buf1, g_buf1);
    cudaGetSymbolAddress((void**)&buf2, g_buf2);
    cudaGetSymbolAddress((void**)&txt,  g_txt);
    cudaGetSymbolAddress((void**)&tq,   g_tq);

    const float inv_sqrt_d = 0.03608439182435161f;  // 1/sqrt(768)
    const float* x = img + DIM;                      // img[:,1:,:] view (batch stride NTOT*DIM)

    // cls passthrough (independent)
    copy_cls_kernel<<<BQ, 256>>>(img, out);

    // 1) scores: S[b] = x x^T / sqrt(D)   (NT)
    gemm_kernel<0, true><<<dim3(4, 4, BQ), 256>>>(
        x, (long)NTOT * DIM, DIM,
        x, (long)NTOT * DIM, DIM,
        attn, (long)NTOK * NTOK, NTOK,
        NTOK, NTOK, DIM, inv_sqrt_d, nullptr, nullptr, nullptr);

    // 2) softmax rows
    softmax_kernel<<<(TTOT * 32 + 255) / 256, 256>>>(attn);

    // 3) msg = A @ x  (NN, batched)
    gemm_kernel<0, false><<<dim3(12, 4, BQ), 256>>>(
        attn, (long)NTOK * NTOK, NTOK,
        x, (long)NTOT * DIM, DIM,
        buf1, (long)NTOK * DIM, DIM,
        NTOK, DIM, NTOK, 1.f, nullptr, nullptr, nullptr);

    // 4) h = gelu(msg @ w1_msg + b1)
    gemm_kernel<1, false><<<dim3(12, (TTOT + 63) / 64, 1), 256>>>(
        buf1, 0, DIM, w1_msg, 0, DIM, buf2, 0, DIM,
        TTOT, DIM, DIM, 1.f, b1_msg, nullptr, nullptr);

    // 5) x_new = x + gamma_gcn*(h @ w2_msg + b2)  -> written into d_out (remapped)
    gemm_kernel<3, false><<<dim3(12, (TTOT + 63) / 64, 1), 256>>>(
        buf2, 0, DIM, w2_msg, 0, DIM, out, 0, 0,
        TTOT, DIM, DIM, 1.f, b2_msg, img, gamma_gcn);

    // 6) text branch: gelu(text @ w1_txt + b1_txt)
    gemm_kernel<1, false><<<dim3(12, 4, 1), 256>>>(
        text, 0, DTXT, w1_txt, 0, DIM, txt, 0, DIM,
        BQ, DIM, DTXT, 1.f, b1_txt, nullptr, nullptr);

    // 7) tq_raw = txt @ w2_txt + b2_txt
    gemm_kernel<2, false><<<dim3(12, 4, 1), 256>>>(
        txt, 0, DIM, w2_txt, 0, DIM, tq, 0, DIM,
        BQ, DIM, DIM, 1.f, b2_txt, nullptr, nullptr);

    // 8) layernorm tq in place
    layernorm_kernel<<<BQ, 256>>>(tq, ln_w, ln_b);

    // 9) gating epilogue in place on d_out token rows
    mask_refine_kernel<<<(TTOT * 32 + 255) / 256, 256>>>(out, tq, gamma);
}

// round 2
// speedup vs baseline: 1.3340x; 1.3340x over previous
#include <cuda_runtime.h>
#include <cstdint>

// Problem dims (fixed by the dataset)
#define BQ   256
#define NTOK 196
#define NTOT 197
#define DIM  768
#define DTXT 512
#define TTOT (BQ*NTOK)   // 50176

// ---------------- scratch (device globals; no allocations allowed) ----------
__device__ float g_attn[(size_t)BQ*NTOK*NTOK];   // scores / softmax(A)
__device__ float g_buf1[(size_t)TTOT*DIM];       // msg
__device__ float g_buf2[(size_t)TTOT*DIM];       // h = gelu(msg@w1+b1)
__device__ float g_txt [(size_t)BQ*DIM];
__device__ float g_tq  [(size_t)BQ*DIM];

__device__ __forceinline__ float gelu_exact(float x) { return x * normcdff(x); }

__device__ __forceinline__ uint32_t f2tf32(float x) {
    uint32_t r; asm("cvt.rna.tf32.f32 %0, %1;" : "=r"(r) : "f"(x)); return r;
}

// =====================================================================
// tf32 tensor-core GEMM:  C = alpha * A(MxK) * op(B) + epilogue
//   BT=false : B is K x N row-major            (NN)
//   BT=true  : B is N x K row-major (B^T used) (NT)
// MODE 0: C = alpha*acc
// MODE 1: C = gelu(acc + bias)
// MODE 3: out[remap] = resid[remap] + g*(acc+bias)
// Block tile 128x128x16, 256 threads (8 warps), warp tile 64x32,
// mma.sync.m16n8k8.tf32. Fragments are pre-permuted into smem so the
// compute phase reads conflict-free LDS.128 / LDS.64.
// =====================================================================
template<int MODE, bool BT>
__launch_bounds__(256)
__global__ void mma_gemm(const float* __restrict__ A, long aBS, int lda,
                         const float* __restrict__ B, long bBS, int ldb,
                         float* __restrict__ C, long cBS, int ldc,
                         int M, int N, int K, float alpha,
                         const float* __restrict__ bias,
                         const float* __restrict__ resid,
                         const float* __restrict__ gscale)
{
    // As: [ks(2)][mt(8)][lane(32)][reg(4)]   Bs: [ks(2)][nt(16)][lane(32)][reg(2)]
    __shared__ uint32_t As[2*8*32*4];
    __shared__ uint32_t Bs[2*16*32*2];

    const int tid  = threadIdx.x;
    const int lane = tid & 31;
    const int wid  = tid >> 5;
    const int wm   = wid & 1;          // warp row  (2 x 64 rows)
    const int wn   = wid >> 1;         // warp col  (4 x 32 cols)
    const int m0   = blockIdx.y * 128;
    const int n0   = blockIdx.x * 128;

    const float* Ab = A + (long)blockIdx.z * aBS;
    const float* Bb = B + (long)blockIdx.z * bBS;

    float acc[4][4][4];
    #pragma unroll
    for (int i = 0; i < 4; i++)
        #pragma unroll
        for (int j = 0; j < 4; j++)
            #pragma unroll
            for (int r = 0; r < 4; r++) acc[i][j][r] = 0.f;

    // A loader: thread covers row (tid>>1), k-chunk 8*(tid&1)
    const int a_m  = tid >> 1;
    const int a_kb = (tid & 1) * 8;

    for (int k0 = 0; k0 < K; k0 += 16) {
        // ---------------- load + permute A tile ----------------
        {
            const int gm = m0 + a_m;
            const int gk = k0 + a_kb;
            float v[8];
            if (gm < M && gk + 7 < K) {
                const float* p = Ab + (long)gm * lda + gk;
                float4 p0 = *reinterpret_cast<const float4*>(p);
                float4 p1 = *reinterpret_cast<const float4*>(p + 4);
                v[0]=p0.x; v[1]=p0.y; v[2]=p0.z; v[3]=p0.w;
                v[4]=p1.x; v[5]=p1.y; v[6]=p1.z; v[7]=p1.w;
            } else {
                #pragma unroll
                for (int j = 0; j < 8; j++)
                    v[j] = (gm < M && gk + j < K) ? Ab[(long)gm * lda + gk + j] : 0.f;
            }
            const int mt = a_m >> 4, mi = a_m & 15;
            const int ks = (tid & 1);
            #pragma unroll
            for (int j = 0; j < 8; j++) {
                int idx = (((ks*8 + mt)*32) + (mi & 7)*4 + (j & 3))*4
                        + ((mi >> 3) + 2*(j >> 2));
                As[idx] = f2tf32(v[j]);
            }
        }
        // ---------------- load + permute B tile ----------------
        if (BT) {
            // B stored N x K: thread covers n-row (tid>>1), k-chunk 8*(tid&1)
            const int gn = n0 + (tid >> 1);
            const int gk = k0 + a_kb;
            float v[8];
            if (gn < N && gk + 7 < K) {
                const float* p = Bb + (long)gn * ldb + gk;
                float4 p0 = *reinterpret_cast<const float4*>(p);
                float4 p1 = *reinterpret_cast<const float4*>(p + 4);
                v[0]=p0.x; v[1]=p0.y; v[2]=p0.z; v[3]=p0.w;
                v[4]=p1.x; v[5]=p1.y; v[6]=p1.z; v[7]=p1.w;
            } else {
                #pragma unroll
                for (int j = 0; j < 8; j++)
                    v[j] = (gn < N && gk + j < K) ? Bb[(long)gn * ldb + gk + j] : 0.f;
            }
            const int nr = tid >> 1;
            const int nt = nr >> 3, ni = nr & 7;
            const int ks = (tid & 1);
            #pragma unroll
            for (int j = 0; j < 8; j++) {
                int idx = (((ks*16 + nt)*32) + ni*4 + (j & 3))*2 + (j >> 2);
                Bs[idx] = f2tf32(v[j]);
            }
        } else {
            // B stored K x N: thread covers k-row (tid>>4), n-chunk 8*(tid&15)
            const int kr = tid >> 4;           // 0..15
            const int gk = k0 + kr;
            const int gn = n0 + (tid & 15) * 8;
            float v[8];
            if (gk < K && gn + 7 < N) {
                const float* p = Bb + (long)gk * ldb + gn;
                float4 p0 = *reinterpret_cast<const float4*>(p);
                float4 p1 = *reinterpret_cast<const float4*>(p + 4);
                v[0]=p0.x; v[1]=p0.y; v[2]=p0.z; v[3]=p0.w;
                v[4]=p1.x; v[5]=p1.y; v[6]=p1.z; v[7]=p1.w;
            } else {
                #pragma unroll
                for (int j = 0; j < 8; j++)
                    v[j] = (gk < K && gn + j < N) ? Bb[(long)gk * ldb + gn + j] : 0.f;
            }
            const int ks = kr >> 3, ki = kr & 7;
            const int nt = tid & 15;
            #pragma unroll
            for (int j = 0; j < 8; j++) {
                int idx = (((ks*16 + nt)*32) + j*4 + (ki & 3))*2 + (ki >> 2);
                Bs[idx] = f2tf32(v[j]);
            }
        }
        __syncthreads();

        // ---------------- compute ----------------
        #pragma unroll
        for (int ks = 0; ks < 2; ks++) {
            uint32_t af[4][4];
            #pragma unroll
            for (int i = 0; i < 4; i++) {
                uint4 t = *reinterpret_cast<const uint4*>(
                    &As[(((ks*8) + wm*4 + i)*32 + lane)*4]);
                af[i][0]=t.x; af[i][1]=t.y; af[i][2]=t.z; af[i][3]=t.w;
            }
            uint32_t bf[4][2];
            #pragma unroll
            for (int j = 0; j < 4; j++) {
                uint2 t = *reinterpret_cast<const uint2*>(
                    &Bs[(((ks*16) + wn*4 + j)*32 + lane)*2]);
                bf[j][0]=t.x; bf[j][1]=t.y;
            }
            #pragma unroll
            for (int i = 0; i < 4; i++)
                #pragma unroll
                for (int j = 0; j < 4; j++) {
                    asm volatile(
                        "mma.sync.aligned.m16n8k8.row.col.f32.tf32.tf32.f32 "
                        "{%0,%1,%2,%3}, {%4,%5,%6,%7}, {%8,%9}, {%0,%1,%2,%3};\n"
                        : "+f"(acc[i][j][0]), "+f"(acc[i][j][1]),
                          "+f"(acc[i][j][2]), "+f"(acc[i][j][3])
                        : "r"(af[i][0]), "r"(af[i][1]), "r"(af[i][2]), "r"(af[i][3]),
                          "r"(bf[j][0]), "r"(bf[j][1]));
                }
        }
        __syncthreads();
    }

    // ---------------- epilogue ----------------
    const float g = (MODE == 3) ? gscale[0] : 0.f;
    const int group = lane >> 2, tg = lane & 3;

    #pragma unroll
    for (int i = 0; i < 4; i++) {
        const int rowB = m0 + wm*64 + i*16;
        #pragma unroll
        for (int j = 0; j < 4; j++) {
            const int colB = n0 + wn*32 + j*8 + tg*2;
            #pragma unroll
            for (int r = 0; r < 4; r++) {
                const int row = rowB + group + ((r >= 2) ? 8 : 0);
                const int col = colB + (r & 1);
                if (row >= M || col >= N) continue;
                float v = acc[i][j][r];
                if (MODE == 0) v *= alpha;
                if (MODE >= 1) v += bias[col];
                if (MODE == 1) v = gelu_exact(v);
                if (MODE == 3) {
                    const int b  = row / NTOK;
                    const int rr = row - b * NTOK;
                    const long off = ((long)b * NTOT + 1 + rr) * DIM + col;
                    C[off] = resid[off] + g * v;
                } else {
                    C[(long)blockIdx.z * cBS + (long)row * ldc + col] = v;
                }
            }
        }
    }
}

// =====================================================================
// SIMT fp32 GEMM (kept for the tiny text-branch GEMMs)
// MODE 1: gelu(acc+bias), MODE 2: acc+bias
// =====================================================================
template<int MODE>
__launch_bounds__(256)
__global__ void gemm_kernel(const float* __restrict__ A, int lda,
                            const float* __restrict__ B, int ldb,
                            float* __restrict__ C, int ldc,
                            int M, int N, int K,
                            const float* __restrict__ bias)
{
    const int BM = 64, BN = 64, BK = 16;
    __shared__ float Ast[BK][BM + 4];
    __shared__ float Bst[BK][BN];

    const int tid = threadIdx.x;
    const int tx = tid & 15, ty = tid >> 4;
    const int m0 = blockIdx.y * BM, n0 = blockIdx.x * BN;

    float acc[4][4] = {};
    const int aRow = tid >> 2, aCol = (tid & 3) * 4;

    for (int k0 = 0; k0 < K; k0 += BK) {
        {
            float4 v = make_float4(0.f,0.f,0.f,0.f);
            int gr = m0 + aRow;
            if (gr < M) {
                int gc = k0 + aCol;
                if (gc + 3 < K) v = *reinterpret_cast<const float4*>(A + (long)gr*lda + gc);
                else {
                    v.x = (gc+0<K)?A[(long)gr*lda+gc+0]:0.f;
                    v.y = (gc+1<K)?A[(long)gr*lda+gc+1]:0.f;
                    v.z = (gc+2<K)?A[(long)gr*lda+gc+2]:0.f;
                    v.w = (gc+3<K)?A[(long)gr*lda+gc+3]:0.f;
                }
            }
            Ast[aCol+0][aRow]=v.x; Ast[aCol+1][aRow]=v.y;
            Ast[aCol+2][aRow]=v.z; Ast[aCol+3][aRow]=v.w;
        }
        {
            int br = tid >> 4, bc = (tid & 15) * 4;
            float4 v = make_float4(0.f,0.f,0.f,0.f);
            int gk = k0 + br, gn = n0 + bc;
            if (gk < K && gn + 3 < N)
                v = *reinterpret_cast<const float4*>(B + (long)gk*ldb + gn);
            else if (gk < K) {
                v.x = (gn+0<N)?B[(long)gk*ldb+gn+0]:0.f;
                v.y = (gn+1<N)?B[(long)gk*ldb+gn+1]:0.f;
                v.z = (gn+2<N)?B[(long)gk*ldb+gn+2]:0.f;
                v.w = (gn+3<N)?B[(long)gk*ldb+gn+3]:0.f;
            }
            *reinterpret_cast<float4*>(&Bst[br][bc]) = v;
        }
        __syncthreads();
        #pragma unroll
        for (int k = 0; k < BK; k++) {
            float4 av = *reinterpret_cast<const float4*>(&Ast[k][ty*4]);
            float4 bv = *reinterpret_cast<const float4*>(&Bst[k][tx*4]);
            acc[0][0]+=av.x*bv.x; acc[0][1]+=av.x*bv.y; acc[0][2]+=av.x*bv.z; acc[0][3]+=av.x*bv.w;
            acc[1][0]+=av.y*bv.x; acc[1][1]+=av.y*bv.y; acc[1][2]+=av.y*bv.z; acc[1][3]+=av.y*bv.w;
            acc[2][0]+=av.z*bv.x; acc[2][1]+=av.z*bv.y; acc[2][2]+=av.z*bv.z; acc[2][3]+=av.z*bv.w;
            acc[3][0]+=av.w*bv.x; acc[3][1]+=av.w*bv.y; acc[3][2]+=av.w*bv.z; acc[3][3]+=av.w*bv.w;
        }
        __syncthreads();
    }

    #pragma unroll
    for (int i = 0; i < 4; i++) {
        int m = m0 + ty*4 + i; if (m >= M) continue;
        #pragma unroll
        for (int j = 0; j < 4; j++) {
            int n = n0 + tx*4 + j; if (n >= N) continue;
            float v = acc[i][j] + bias[n];
            if (MODE == 1) v = gelu_exact(v);
            C[(long)m*ldc + n] = v;
        }
    }
}

// ---------------- softmax over rows of g_attn (one warp per row) -------------
__global__ void softmax_kernel(float* __restrict__ S)
{
    int warp = (blockIdx.x * blockDim.x + threadIdx.x) >> 5;
    int lane = threadIdx.x & 31;
    if (warp >= (int)(BQ * NTOK)) return;
    float* p = S + (long)warp * NTOK;

    float v[7];
    float mx = -3.0e38f;
    #pragma unroll
    for (int it = 0; it < 7; it++) {
        int j = lane + it * 32;
        v[it] = (j < NTOK) ? p[j] : -3.0e38f;
        mx = fmaxf(mx, v[it]);
    }
    #pragma unroll
    for (int o = 16; o; o >>= 1) mx = fmaxf(mx, __shfl_xor_sync(0xffffffffu, mx, o));

    float s = 0.f;
    #pragma unroll
    for (int it = 0; it < 7; it++) {
        int j = lane + it * 32;
        if (j < NTOK) { v[it] = expf(v[it] - mx); s += v[it]; } else v[it] = 0.f;
    }
    #pragma unroll
    for (int o = 16; o; o >>= 1) s += __shfl_xor_sync(0xffffffffu, s, o);
    float inv = 1.f / s;
    #pragma unroll
    for (int it = 0; it < 7; it++) {
        int j = lane + it * 32;
        if (j < NTOK) p[j] = v[it] * inv;
    }
}

// ---------------- layernorm rows of g_tq in place ----------------------------
__global__ void layernorm_kernel(float* __restrict__ X,
                                 const float* __restrict__ w,
                                 const float* __restrict__ b)
{
    int row = blockIdx.x;
    float* p = X + (long)row * DIM;
    float s = 0.f, sq = 0.f;
    for (int j = threadIdx.x; j < DIM; j += blockDim.x) {
        float x = p[j]; s += x; sq += x * x;
    }
    __shared__ float rs[32], rq[32];
    int lane = threadIdx.x & 31, wid = threadIdx.x >> 5;
    #pragma unroll
    for (int o = 16; o; o >>= 1) {
        s  += __shfl_xor_sync(0xffffffffu, s, o);
        sq += __shfl_xor_sync(0xffffffffu, sq, o);
    }
    if (lane == 0) { rs[wid] = s; rq[wid] = sq; }
    __syncthreads();
    int nw = blockDim.x >> 5;
    if (wid == 0) {
        float a = (lane < nw) ? rs[lane] : 0.f;
        float c = (lane < nw) ? rq[lane] : 0.f;
        #pragma unroll
        for (int o = 16; o; o >>= 1) {
            a += __shfl_xor_sync(0xffffffffu, a, o);
            c += __shfl_xor_sync(0xffffffffu, c, o);
        }
        if (lane == 0) { rs[0] = a; rq[0] = c; }
    }
    __syncthreads();
    float mu  = rs[0] / DIM;
    float var = rq[0] / DIM - mu * mu;
    float rstd = rsqrtf(var + 1e-5f);
    for (int j = threadIdx.x; j < DIM; j += blockDim.x)
        p[j] = (p[j] - mu) * rstd * w[j] + b[j];
}

// ----- gating: out_row *= (1 + gamma*sigmoid(dot(out_row, tq_b)))  (in place)
__global__ void mask_refine_kernel(float* __restrict__ out,
                                   const float* __restrict__ tq,
                                   const float* __restrict__ gamma)
{
    int warp = (blockIdx.x * blockDim.x + threadIdx.x) >> 5;
    int lane = threadIdx.x & 31;
    if (warp >= (int)TTOT) return;
    int b = warp / NTOK;
    int r = warp - b * NTOK;
    float* p = out + ((long)b * NTOT + 1 + r) * DIM;
    const float* t = tq + (long)b * DIM;
    float d = 0.f;
    for (int j = lane; j < DIM; j += 32) d += p[j] * t[j];
    #pragma unroll
    for (int o = 16; o; o >>= 1) d += __shfl_xor_sync(0xffffffffu, d, o);
    float m  = 1.f / (1.f + expf(-d));
    float sc = 1.f + gamma[0] * m;
    for (int j = lane; j < DIM; j += 32) p[j] *= sc;
}

// ---------------- cls passthrough --------------------------------------------
__global__ void copy_cls_kernel(const float* __restrict__ img, float* __restrict__ out)
{
    int b = blockIdx.x;
    long base = (long)b * NTOT * DIM;
    for (int j = threadIdx.x; j < DIM; j += blockDim.x)
        out[base + j] = img[base + j];
}

// =====================================================================
extern "C" void kernel_launch(void* const* d_in, const int* in_sizes, int n_in,
                              void* d_out, int out_size)
{
    const float* img       = (const float*)d_in[0];
    const float* text      = (const float*)d_in[1];
    const float* w1_msg    = (const float*)d_in[2];
    const float* b1_msg    = (const float*)d_in[3];
    const float* w2_msg    = (const float*)d_in[4];
    const float* b2_msg    = (const float*)d_in[5];
    const float* gamma_gcn = (const float*)d_in[6];
    const float* w1_txt    = (const float*)d_in[7];
    const float* b1_txt    = (const float*)d_in[8];
    const float* w2_txt    = (const float*)d_in[9];
    const float* b2_txt    = (const float*)d_in[10];
    const float* ln_w      = (const float*)d_in[11];
    const float* ln_b      = (const float*)d_in[12];
    const float* gamma     = (const float*)d_in[13];
    float* out = (float*)d_out;

    float *attn, *buf1, *buf2, *txt, *tq;
    cudaGetSymbolAddress((void**)&attn, g_attn);
    cudaGetSymbolAddress((void**)&buf1, g_buf1);
    cudaGetSymbolAddress((void**)&buf2, g_buf2);
    cudaGetSymbolAddress((void**)&txt,  g_txt);
    cudaGetSymbolAddress((void**)&tq,   g_tq);

    const float inv_sqrt_d = 0.03608439182435161f;  // 1/sqrt(768)
    const float* x = img + DIM;   // img[:,1:,:] view (batch stride NTOT*DIM)

    // cls passthrough (independent)
    copy_cls_kernel<<<BQ, 256>>>(img, out);

    // 1) scores: S[b] = x x^T / sqrt(D)   (NT, tf32 tensor)
    mma_gemm<0, true><<<dim3(2, 2, BQ), 256>>>(
        x, (long)NTOT * DIM, DIM,
        x, (long)NTOT * DIM, DIM,
        attn, (long)NTOK * NTOK, NTOK,
        NTOK, NTOK, DIM, inv_sqrt_d, nullptr, nullptr, nullptr);

    // 2) softmax rows
    softmax_kernel<<<(TTOT * 32 + 255) / 256, 256>>>(attn);

    // 3) msg = A @ x  (NN, batched, tf32 tensor)
    mma_gemm<0, false><<<dim3(6, 2, BQ), 256>>>(
        attn, (long)NTOK * NTOK, NTOK,
        x, (long)NTOT * DIM, DIM,
        buf1, (long)NTOK * DIM, DIM,
        NTOK, DIM, NTOK, 1.f, nullptr, nullptr, nullptr);

    // 4) h = gelu(msg @ w1_msg + b1)   (tf32 tensor)
    mma_gemm<1, false><<<dim3(6, TTOT / 128, 1), 256>>>(
        buf1, 0, DIM, w1_msg, 0, DIM, buf2, 0, DIM,
        TTOT, DIM, DIM, 1.f, b1_msg, nullptr, nullptr);

    // 5) x_new = x + gamma_gcn*(h @ w2_msg + b2) -> d_out (remapped)
    mma_gemm<3, false><<<dim3(6, TTOT / 128, 1), 256>>>(
        buf2, 0, DIM, w2_msg, 0, DIM, out, 0, 0,
        TTOT, DIM, DIM, 1.f, b2_msg, img, gamma_gcn);

    // 6) text branch: gelu(text @ w1_txt + b1_txt)   (small, SIMT fp32)
    gemm_kernel<1><<<dim3(12, 4, 1), 256>>>(
        text, DTXT, w1_txt, DIM, txt, DIM, BQ, DIM, DTXT, b1_txt);

    // 7) tq_raw = txt @ w2_txt + b2_txt
    gemm_kernel<2><<<dim3(12, 4, 1), 256>>>(
        txt, DIM, w2_txt, DIM, tq, DIM, BQ, DIM, DIM, b2_txt);

    // 8) layernorm tq in place
    layernorm_kernel<<<BQ, 256>>>(tq, ln_w, ln_b);

    // 9) gating epilogue in place on d_out token rows
    mask_refine_kernel<<<(TTOT * 32 + 255) / 256, 256>>>(out, tq, gamma);
}

// round 3
// speedup vs baseline: 1.5217x; 1.1407x over previous
#include <cuda_runtime.h>
#include <cstdint>

// Problem dims (fixed by the dataset)
#define BQ   256
#define NTOK 196
#define NTOT 197
#define DIM  768
#define DTXT 512
#define TTOT (BQ*NTOK)   // 50176

// ---------------- scratch (device globals; no allocations allowed) ----------
__device__ float g_attn[(size_t)BQ*NTOK*NTOK];
__device__ float g_buf1[(size_t)TTOT*DIM];
__device__ float g_buf2[(size_t)TTOT*DIM];
__device__ float g_txt [(size_t)BQ*DIM];
__device__ float g_tq  [(size_t)BQ*DIM];

__device__ __forceinline__ float gelu_exact(float x) { return x * normcdff(x); }

__device__ __forceinline__ uint32_t f2tf32(float x) {
    uint32_t r; asm("cvt.rna.tf32.f32 %0, %1;" : "=r"(r) : "f"(x)); return r;
}

// =====================================================================
// tf32 tensor-core GEMM, software-pipelined:
//   C = alpha * A(MxK) * op(B) + epilogue
//   BT=false : B is K x N row-major (NN);  BT=true : B is N x K (NT)
// MODE 0: C = alpha*acc
// MODE 1: C = gelu(acc + bias)
// MODE 3: out[remap] = resid[remap] + g*(acc+bias)
// Block 128x128x16, 8 warps, warp tile 64x32, mma.m16n8k8.tf32.
// Double-buffered smem + register-staged gmem prefetch: one sync/iter.
// =====================================================================
template<int MODE, bool BT>
__launch_bounds__(256, 2)
__global__ void mma_gemm(const float* __restrict__ A, long aBS, int lda,
                         const float* __restrict__ B, long bBS, int ldb,
                         float* __restrict__ C, long cBS, int ldc,
                         int M, int N, int K, float alpha,
                         const float* __restrict__ bias,
                         const float* __restrict__ resid,
                         const float* __restrict__ gscale)
{
    // per buffer: As 2048 u32 (8KB), Bs 2048 u32 (8KB); x2 buffers = 32KB
    __shared__ uint32_t As[2][2*8*32*4];
    __shared__ uint32_t Bs[2][2*16*32*2];

    const int tid  = threadIdx.x;
    const int lane = tid & 31;
    const int wid  = tid >> 5;
    const int wm   = wid & 1;
    const int wn   = wid >> 1;
    const int m0   = blockIdx.y * 128;
    const int n0   = blockIdx.x * 128;

    const float* Ab = A + (long)blockIdx.z * aBS;
    const float* Bb = B + (long)blockIdx.z * bBS;

    float acc[4][4][4];
    #pragma unroll
    for (int i = 0; i < 4; i++)
        #pragma unroll
        for (int j = 0; j < 4; j++)
            #pragma unroll
            for (int r = 0; r < 4; r++) acc[i][j][r] = 0.f;

    // loader geometry (fixed per thread)
    const int a_m  = tid >> 1;          // A row within tile (0..127)
    const int a_kb = (tid & 1) * 8;     // A k-chunk base (0 or 8)
    float vA[8], vB[8];

    // ---- gmem load helpers (guarded) ----
    auto loadA = [&](int k0) {
        const int gm = m0 + a_m;
        const int gk = k0 + a_kb;
        if (gm < M && gk + 7 < K) {
            const float* p = Ab + (long)gm * lda + gk;
            float4 p0 = *reinterpret_cast<const float4*>(p);
            float4 p1 = *reinterpret_cast<const float4*>(p + 4);
            vA[0]=p0.x; vA[1]=p0.y; vA[2]=p0.z; vA[3]=p0.w;
            vA[4]=p1.x; vA[5]=p1.y; vA[6]=p1.z; vA[7]=p1.w;
        } else {
            #pragma unroll
            for (int j = 0; j < 8; j++)
                vA[j] = (gm < M && gk + j < K) ? Ab[(long)gm * lda + gk + j] : 0.f;
        }
    };
    auto loadB = [&](int k0) {
        if (BT) {
            const int gn = n0 + (tid >> 1);
            const int gk = k0 + a_kb;
            if (gn < N && gk + 7 < K) {
                const float* p = Bb + (long)gn * ldb + gk;
                float4 p0 = *reinterpret_cast<const float4*>(p);
                float4 p1 = *reinterpret_cast<const float4*>(p + 4);
                vB[0]=p0.x; vB[1]=p0.y; vB[2]=p0.z; vB[3]=p0.w;
                vB[4]=p1.x; vB[5]=p1.y; vB[6]=p1.z; vB[7]=p1.w;
            } else {
                #pragma unroll
                for (int j = 0; j < 8; j++)
                    vB[j] = (gn < N && gk + j < K) ? Bb[(long)gn * ldb + gk + j] : 0.f;
            }
        } else {
            const int kr = tid >> 4;
            const int gk = k0 + kr;
            const int gn = n0 + (tid & 15) * 8;
            if (gk < K && gn + 7 < N) {
                const float* p = Bb + (long)gk * ldb + gn;
                float4 p0 = *reinterpret_cast<const float4*>(p);
                float4 p1 = *reinterpret_cast<const float4*>(p + 4);
                vB[0]=p0.x; vB[1]=p0.y; vB[2]=p0.z; vB[3]=p0.w;
                vB[4]=p1.x; vB[5]=p1.y; vB[6]=p1.z; vB[7]=p1.w;
            } else {
                #pragma unroll
                for (int j = 0; j < 8; j++)
                    vB[j] = (gk < K && gn + j < N) ? Bb[(long)gk * ldb + gn + j] : 0.f;
            }
        }
    };
    // ---- smem permuted store helpers ----
    auto storeA = [&](int buf) {
        const int mt = a_m >> 4, mi = a_m & 15;
        const int ks = (tid & 1);
        #pragma unroll
        for (int j = 0; j < 8; j++) {
            int idx = (((ks*8 + mt)*32) + (mi & 7)*4 + (j & 3))*4
                    + ((mi >> 3) + 2*(j >> 2));
            As[buf][idx] = f2tf32(vA[j]);
        }
    };
    auto storeB = [&](int buf) {
        if (BT) {
            const int nr = tid >> 1;
            const int nt = nr >> 3, ni = nr & 7;
            const int ks = (tid & 1);
            #pragma unroll
            for (int j = 0; j < 8; j++) {
                int idx = (((ks*16 + nt)*32) + ni*4 + (j & 3))*2 + (j >> 2);
                Bs[buf][idx] = f2tf32(vB[j]);
            }
        } else {
            const int kr = tid >> 4;
            const int ks = kr >> 3, ki = kr & 7;
            const int nt = tid & 15;
            #pragma unroll
            for (int j = 0; j < 8; j++) {
                int idx = (((ks*16 + nt)*32) + j*4 + (ki & 3))*2 + (ki >> 2);
                Bs[buf][idx] = f2tf32(vB[j]);
            }
        }
    };

    // ---------------- prologue: fill buffer 0 ----------------
    loadA(0); loadB(0);
    storeA(0); storeB(0);
    __syncthreads();

    int cur = 0;
    for (int k0 = 0; k0 < K; k0 += 16) {
        const bool has_next = (k0 + 16) < K;
        // 1) prefetch next tile into registers (overlaps with compute)
        if (has_next) { loadA(k0 + 16); loadB(k0 + 16); }

        // 2) compute on current buffer
        #pragma unroll
        for (int ks = 0; ks < 2; ks++) {
            uint32_t af[4][4];
            #pragma unroll
            for (int i = 0; i < 4; i++) {
                uint4 t = *reinterpret_cast<const uint4*>(
                    &As[cur][(((ks*8) + wm*4 + i)*32 + lane)*4]);
                af[i][0]=t.x; af[i][1]=t.y; af[i][2]=t.z; af[i][3]=t.w;
            }
            uint32_t bf[4][2];
            #pragma unroll
            for (int j = 0; j < 4; j++) {
                uint2 t = *reinterpret_cast<const uint2*>(
                    &Bs[cur][(((ks*16) + wn*4 + j)*32 + lane)*2]);
                bf[j][0]=t.x; bf[j][1]=t.y;
            }
            #pragma unroll
            for (int i = 0; i < 4; i++)
                #pragma unroll
                for (int j = 0; j < 4; j++) {
                    asm volatile(
                        "mma.sync.aligned.m16n8k8.row.col.f32.tf32.tf32.f32 "
                        "{%0,%1,%2,%3}, {%4,%5,%6,%7}, {%8,%9}, {%0,%1,%2,%3};\n"
                        : "+f"(acc[i][j][0]), "+f"(acc[i][j][1]),
                          "+f"(acc[i][j][2]), "+f"(acc[i][j][3])
                        : "r"(af[i][0]), "r"(af[i][1]), "r"(af[i][2]), "r"(af[i][3]),
                          "r"(bf[j][0]), "r"(bf[j][1]));
                }
        }

        // 3) commit prefetched tile to the other buffer
        if (has_next) { storeA(cur ^ 1); storeB(cur ^ 1); }
        __syncthreads();
        cur ^= 1;
    }

    // ---------------- epilogue ----------------
    const float g = (MODE == 3) ? gscale[0] : 0.f;
    const int group = lane >> 2, tg = lane & 3;

    #pragma unroll
    for (int i = 0; i < 4; i++) {
        const int rowB = m0 + wm*64 + i*16;
        #pragma unroll
        for (int j = 0; j < 4; j++) {
            const int colB = n0 + wn*32 + j*8 + tg*2;
            #pragma unroll
            for (int r = 0; r < 4; r++) {
                const int row = rowB + group + ((r >= 2) ? 8 : 0);
                const int col = colB + (r & 1);
                if (row >= M || col >= N) continue;
                float v = acc[i][j][r];
                if (MODE == 0) v *= alpha;
                if (MODE >= 1) v += bias[col];
                if (MODE == 1) v = gelu_exact(v);
                if (MODE == 3) {
                    const int b  = row / NTOK;
                    const int rr = row - b * NTOK;
                    const long off = ((long)b * NTOT + 1 + rr) * DIM + col;
                    C[off] = resid[off] + g * v;
                } else {
                    C[(long)blockIdx.z * cBS + (long)row * ldc + col] = v;
                }
            }
        }
    }
}

// =====================================================================
// SIMT fp32 GEMM (tiny text-branch GEMMs)
// =====================================================================
template<int MODE>
__launch_bounds__(256)
__global__ void gemm_kernel(const float* __restrict__ A, int lda,
                            const float* __restrict__ B, int ldb,
                            float* __restrict__ C, int ldc,
                            int M, int N, int K,
                            const float* __restrict__ bias)
{
    const int BM = 64, BN = 64, BK = 16;
    __shared__ float Ast[BK][BM + 4];
    __shared__ float Bst[BK][BN];

    const int tid = threadIdx.x;
    const int tx = tid & 15, ty = tid >> 4;
    const int m0 = blockIdx.y * BM, n0 = blockIdx.x * BN;

    float acc[4][4] = {};
    const int aRow = tid >> 2, aCol = (tid & 3) * 4;

    for (int k0 = 0; k0 < K; k0 += BK) {
        {
            float4 v = make_float4(0.f,0.f,0.f,0.f);
            int gr = m0 + aRow;
            if (gr < M) {
                int gc = k0 + aCol;
                if (gc + 3 < K) v = *reinterpret_cast<const float4*>(A + (long)gr*lda + gc);
                else {
                    v.x = (gc+0<K)?A[(long)gr*lda+gc+0]:0.f;
                    v.y = (gc+1<K)?A[(long)gr*lda+gc+1]:0.f;
                    v.z = (gc+2<K)?A[(long)gr*lda+gc+2]:0.f;
                    v.w = (gc+3<K)?A[(long)gr*lda+gc+3]:0.f;
                }
            }
            Ast[aCol+0][aRow]=v.x; Ast[aCol+1][aRow]=v.y;
            Ast[aCol+2][aRow]=v.z; Ast[aCol+3][aRow]=v.w;
        }
        {
            int br = tid >> 4, bc = (tid & 15) * 4;
            float4 v = make_float4(0.f,0.f,0.f,0.f);
            int gk = k0 + br, gn = n0 + bc;
            if (gk < K && gn + 3 < N)
                v = *reinterpret_cast<const float4*>(B + (long)gk*ldb + gn);
            else if (gk < K) {
                v.x = (gn+0<N)?B[(long)gk*ldb+gn+0]:0.f;
                v.y = (gn+1<N)?B[(long)gk*ldb+gn+1]:0.f;
                v.z = (gn+2<N)?B[(long)gk*ldb+gn+2]:0.f;
                v.w = (gn+3<N)?B[(long)gk*ldb+gn+3]:0.f;
            }
            *reinterpret_cast<float4*>(&Bst[br][bc]) = v;
        }
        __syncthreads();
        #pragma unroll
        for (int k = 0; k < BK; k++) {
            float4 av = *reinterpret_cast<const float4*>(&Ast[k][ty*4]);
            float4 bv = *reinterpret_cast<const float4*>(&Bst[k][tx*4]);
            acc[0][0]+=av.x*bv.x; acc[0][1]+=av.x*bv.y; acc[0][2]+=av.x*bv.z; acc[0][3]+=av.x*bv.w;
            acc[1][0]+=av.y*bv.x; acc[1][1]+=av.y*bv.y; acc[1][2]+=av.y*bv.z; acc[1][3]+=av.y*bv.w;
            acc[2][0]+=av.z*bv.x; acc[2][1]+=av.z*bv.y; acc[2][2]+=av.z*bv.z; acc[2][3]+=av.z*bv.w;
            acc[3][0]+=av.w*bv.x; acc[3][1]+=av.w*bv.y; acc[3][2]+=av.w*bv.z; acc[3][3]+=av.w*bv.w;
        }
        __syncthreads();
    }

    #pragma unroll
    for (int i = 0; i < 4; i++) {
        int m = m0 + ty*4 + i; if (m >= M) continue;
        #pragma unroll
        for (int j = 0; j < 4; j++) {
            int n = n0 + tx*4 + j; if (n >= N) continue;
            float v = acc[i][j] + bias[n];
            if (MODE == 1) v = gelu_exact(v);
            C[(long)m*ldc + n] = v;
        }
    }
}

// ---------------- softmax over rows of g_attn (one warp per row) -------------
__global__ void softmax_kernel(float* __restrict__ S)
{
    int warp = (blockIdx.x * blockDim.x + threadIdx.x) >> 5;
    int lane = threadIdx.x & 31;
    if (warp >= (int)(BQ * NTOK)) return;
    float* p = S + (long)warp * NTOK;

    float v[7];
    float mx = -3.0e38f;
    #pragma unroll
    for (int it = 0; it < 7; it++) {
        int j = lane + it * 32;
        v[it] = (j < NTOK) ? p[j] : -3.0e38f;
        mx = fmaxf(mx, v[it]);
    }
    #pragma unroll
    for (int o = 16; o; o >>= 1) mx = fmaxf(mx, __shfl_xor_sync(0xffffffffu, mx, o));

    float s = 0.f;
    #pragma unroll
    for (int it = 0; it < 7; it++) {
        int j = lane + it * 32;
        if (j < NTOK) { v[it] = expf(v[it] - mx); s += v[it]; } else v[it] = 0.f;
    }
    #pragma unroll
    for (int o = 16; o; o >>= 1) s += __shfl_xor_sync(0xffffffffu, s, o);
    float inv = 1.f / s;
    #pragma unroll
    for (int it = 0; it < 7; it++) {
        int j = lane + it * 32;
        if (j < NTOK) p[j] = v[it] * inv;
    }
}

// ---------------- layernorm rows of g_tq in place ----------------------------
__global__ void layernorm_kernel(float* __restrict__ X,
                                 const float* __restrict__ w,
                                 const float* __restrict__ b)
{
    int row = blockIdx.x;
    float* p = X + (long)row * DIM;
    float s = 0.f, sq = 0.f;
    for (int j = threadIdx.x; j < DIM; j += blockDim.x) {
        float x = p[j]; s += x; sq += x * x;
    }
    __shared__ float rs[32], rq[32];
    int lane = threadIdx.x & 31, wid = threadIdx.x >> 5;
    #pragma unroll
    for (int o = 16; o; o >>= 1) {
        s  += __shfl_xor_sync(0xffffffffu, s, o);
        sq += __shfl_xor_sync(0xffffffffu, sq, o);
    }
    if (lane == 0) { rs[wid] = s; rq[wid] = sq; }
    __syncthreads();
    int nw = blockDim.x >> 5;
    if (wid == 0) {
        float a = (lane < nw) ? rs[lane] : 0.f;
        float c = (lane < nw) ? rq[lane] : 0.f;
        #pragma unroll
        for (int o = 16; o; o >>= 1) {
            a += __shfl_xor_sync(0xffffffffu, a, o);
            c += __shfl_xor_sync(0xffffffffu, c, o);
        }
        if (lane == 0) { rs[0] = a; rq[0] = c; }
    }
    __syncthreads();
    float mu  = rs[0] / DIM;
    float var = rq[0] / DIM - mu * mu;
    float rstd = rsqrtf(var + 1e-5f);
    for (int j = threadIdx.x; j < DIM; j += blockDim.x)
        p[j] = (p[j] - mu) * rstd * w[j] + b[j];
}

// ----- gating: out_row *= (1 + gamma*sigmoid(dot(out_row, tq_b)))  (in place)
__global__ void mask_refine_kernel(float* __restrict__ out,
                                   const float* __restrict__ tq,
                                   const float* __restrict__ gamma)
{
    int warp = (blockIdx.x * blockDim.x + threadIdx.x) >> 5;
    int lane = threadIdx.x & 31;
    if (warp >= (int)TTOT) return;
    int b = warp / NTOK;
    int r = warp - b * NTOK;
    float* p = out + ((long)b * NTOT + 1 + r) * DIM;
    const float* t = tq + (long)b * DIM;
    float d = 0.f;
    for (int j = lane; j < DIM; j += 32) d += p[j] * t[j];
    #pragma unroll
    for (int o = 16; o; o >>= 1) d += __shfl_xor_sync(0xffffffffu, d, o);
    float m  = 1.f / (1.f + expf(-d));
    float sc = 1.f + gamma[0] * m;
    for (int j = lane; j < DIM; j += 32) p[j] *= sc;
}

// ---------------- cls passthrough --------------------------------------------
__global__ void copy_cls_kernel(const float* __restrict__ img, float* __restrict__ out)
{
    int b = blockIdx.x;
    long base = (long)b * NTOT * DIM;
    for (int j = threadIdx.x; j < DIM; j += blockDim.x)
        out[base + j] = img[base + j];
}

// =====================================================================
extern "C" void kernel_launch(void* const* d_in, const int* in_sizes, int n_in,
                              void* d_out, int out_size)
{
    const float* img       = (const float*)d_in[0];
    const float* text      = (const float*)d_in[1];
    const float* w1_msg    = (const float*)d_in[2];
    const float* b1_msg    = (const float*)d_in[3];
    const float* w2_msg    = (const float*)d_in[4];
    const float* b2_msg    = (const float*)d_in[5];
    const float* gamma_gcn = (const float*)d_in[6];
    const float* w1_txt    = (const float*)d_in[7];
    const float* b1_txt    = (const float*)d_in[8];
    const float* w2_txt    = (const float*)d_in[9];
    const float* b2_txt    = (const float*)d_in[10];
    const float* ln_w      = (const float*)d_in[11];
    const float* ln_b      = (const float*)d_in[12];
    const float* gamma     = (const float*)d_in[13];
    float* out = (float*)d_out;

    float *attn, *buf1, *buf2, *txt, *tq;
    cudaGetSymbolAddress((void**)&attn, g_attn);
    cudaGetSymbolAddress((void**)&buf1, g_buf1);
    cudaGetSymbolAddress((void**)&buf2, g_buf2);
    cudaGetSymbolAddress((void**)&txt,  g_txt);
    cudaGetSymbolAddress((void**)&tq,   g_tq);

    const float inv_sqrt_d = 0.03608439182435161f;  // 1/sqrt(768)
    const float* x = img + DIM;   // img[:,1:,:] view (batch stride NTOT*DIM)

    copy_cls_kernel<<<BQ, 256>>>(img, out);

    // 1) scores: S[b] = x x^T / sqrt(D)   (NT)
    mma_gemm<0, true><<<dim3(2, 2, BQ), 256>>>(
        x, (long)NTOT * DIM, DIM,
        x, (long)NTOT * DIM, DIM,
        attn, (long)NTOK * NTOK, NTOK,
        NTOK, NTOK, DIM, inv_sqrt_d, nullptr, nullptr, nullptr);

    // 2) softmax rows
    softmax_kernel<<<(TTOT * 32 + 255) / 256, 256>>>(attn);

    // 3) msg = A @ x  (NN, batched)
    mma_gemm<0, false><<<dim3(6, 2, BQ), 256>>>(
        attn, (long)NTOK * NTOK, NTOK,
        x, (long)NTOT * DIM, DIM,
        buf1, (long)NTOK * DIM, DIM,
        NTOK, DIM, NTOK, 1.f, nullptr, nullptr, nullptr);

    // 4) h = gelu(msg @ w1_msg + b1)
    mma_gemm<1, false><<<dim3(6, TTOT / 128, 1), 256>>>(
        buf1, 0, DIM, w1_msg, 0, DIM, buf2, 0, DIM,
        TTOT, DIM, DIM, 1.f, b1_msg, nullptr, nullptr);

    // 5) x_new = x + gamma_gcn*(h @ w2_msg + b2) -> d_out (remapped)
    mma_gemm<3, false><<<dim3(6, TTOT / 128, 1), 256>>>(
        buf2, 0, DIM, w2_msg, 0, DIM, out, 0, 0,
        TTOT, DIM, DIM, 1.f, b2_msg, img, gamma_gcn);

    // 6) text branch
    gemm_kernel<1><<<dim3(12, 4, 1), 256>>>(
        text, DTXT, w1_txt, DIM, txt, DIM, BQ, DIM, DTXT, b1_txt);
    gemm_kernel<2><<<dim3(12, 4, 1), 256>>>(
        txt, DIM, w2_txt, DIM, tq, DIM, BQ, DIM, DIM, b2_txt);
    layernorm_kernel<<<BQ, 256>>>(tq, ln_w, ln_b);

    // 9) gating epilogue in place on d_out token rows
    mask_refine_kernel<<<(TTOT * 32 + 255) / 256, 256>>>(out, tq, gamma);
}

// round 4
// speedup vs baseline: 1.5241x; 1.0016x over previous
#include <cuda_runtime.h>
#include <cstdint>

// Problem dims (fixed by the dataset)
#define BQ   256
#define NTOK 196
#define NTOT 197
#define DIM  768
#define DTXT 512
#define TTOT (BQ*NTOK)   // 50176

// ---------------- scratch (device globals; no allocations allowed) ----------
__device__ float g_attn[(size_t)BQ*NTOK*NTOK];
__device__ float g_buf1[(size_t)TTOT*DIM];
__device__ float g_buf2[(size_t)TTOT*DIM];
__device__ float g_txt [(size_t)BQ*DIM];
__device__ float g_tq  [(size_t)BQ*DIM];

__device__ __forceinline__ float gelu_exact(float x) { return x * normcdff(x); }

__device__ __forceinline__ uint32_t f2tf32(float x) {
    uint32_t r; asm("cvt.rna.tf32.f32 %0, %1;" : "=r"(r) : "f"(x)); return r;
}

// =====================================================================
// tf32 tensor-core GEMM, software-pipelined:
//   C = alpha * A(MxK) * op(B) + epilogue
//   BT=false : B is K x N row-major (NN);  BT=true : B is N x K (NT)
// MODE 0: C = alpha*acc
// MODE 1: C = gelu(acc + bias)
// MODE 3: out[remap] = resid[remap] + g*(acc+bias)
// Block 128x128x16, 8 warps, warp tile 64x32, mma.m16n8k8.tf32.
// Double-buffered smem + register-staged gmem prefetch: one sync/iter.
// =====================================================================
template<int MODE, bool BT>
__launch_bounds__(256, 2)
__global__ void mma_gemm(const float* __restrict__ A, long aBS, int lda,
                         const float* __restrict__ B, long bBS, int ldb,
                         float* __restrict__ C, long cBS, int ldc,
                         int M, int N, int K, float alpha,
                         const float* __restrict__ bias,
                         const float* __restrict__ resid,
                         const float* __restrict__ gscale)
{
    // per buffer: As 2048 u32 (8KB), Bs 2048 u32 (8KB); x2 buffers = 32KB
    __shared__ uint32_t As[2][2*8*32*4];
    __shared__ uint32_t Bs[2][2*16*32*2];

    const int tid  = threadIdx.x;
    const int lane = tid & 31;
    const int wid  = tid >> 5;
    const int wm   = wid & 1;
    const int wn   = wid >> 1;
    const int m0   = blockIdx.y * 128;
    const int n0   = blockIdx.x * 128;

    const float* Ab = A + (long)blockIdx.z * aBS;
    const float* Bb = B + (long)blockIdx.z * bBS;

    float acc[4][4][4];
    #pragma unroll
    for (int i = 0; i < 4; i++)
        #pragma unroll
        for (int j = 0; j < 4; j++)
            #pragma unroll
            for (int r = 0; r < 4; r++) acc[i][j][r] = 0.f;

    // loader geometry (fixed per thread)
    const int a_m  = tid >> 1;          // A row within tile (0..127)
    const int a_kb = (tid & 1) * 8;     // A k-chunk base (0 or 8)
    float vA[8], vB[8];

    // ---- gmem load helpers (guarded) ----
    auto loadA = [&](int k0) {
        const int gm = m0 + a_m;
        const int gk = k0 + a_kb;
        if (gm < M && gk + 7 < K) {
            const float* p = Ab + (long)gm * lda + gk;
            float4 p0 = *reinterpret_cast<const float4*>(p);
            float4 p1 = *reinterpret_cast<const float4*>(p + 4);
            vA[0]=p0.x; vA[1]=p0.y; vA[2]=p0.z; vA[3]=p0.w;
            vA[4]=p1.x; vA[5]=p1.y; vA[6]=p1.z; vA[7]=p1.w;
        } else {
            #pragma unroll
            for (int j = 0; j < 8; j++)
                vA[j] = (gm < M && gk + j < K) ? Ab[(long)gm * lda + gk + j] : 0.f;
        }
    };
    auto loadB = [&](int k0) {
        if (BT) {
            const int gn = n0 + (tid >> 1);
            const int gk = k0 + a_kb;
            if (gn < N && gk + 7 < K) {
                const float* p = Bb + (long)gn * ldb + gk;
                float4 p0 = *reinterpret_cast<const float4*>(p);
                float4 p1 = *reinterpret_cast<const float4*>(p + 4);
                vB[0]=p0.x; vB[1]=p0.y; vB[2]=p0.z; vB[3]=p0.w;
                vB[4]=p1.x; vB[5]=p1.y; vB[6]=p1.z; vB[7]=p1.w;
            } else {
                #pragma unroll
                for (int j = 0; j < 8; j++)
                    vB[j] = (gn < N && gk + j < K) ? Bb[(long)gn * ldb + gk + j] : 0.f;
            }
        } else {
            const int kr = tid >> 4;
            const int gk = k0 + kr;
            const int gn = n0 + (tid & 15) * 8;
            if (gk < K && gn + 7 < N) {
                const float* p = Bb + (long)gk * ldb + gn;
                float4 p0 = *reinterpret_cast<const float4*>(p);
                float4 p1 = *reinterpret_cast<const float4*>(p + 4);
                vB[0]=p0.x; vB[1]=p0.y; vB[2]=p0.z; vB[3]=p0.w;
                vB[4]=p1.x; vB[5]=p1.y; vB[6]=p1.z; vB[7]=p1.w;
            } else {
                #pragma unroll
                for (int j = 0; j < 8; j++)
                    vB[j] = (gk < K && gn + j < N) ? Bb[(long)gk * ldb + gn + j] : 0.f;
            }
        }
    };
    // ---- smem permuted store helpers ----
    auto storeA = [&](int buf) {
        const int mt = a_m >> 4, mi = a_m & 15;
        const int ks = (tid & 1);
        #pragma unroll
        for (int j = 0; j < 8; j++) {
            int idx = (((ks*8 + mt)*32) + (mi & 7)*4 + (j & 3))*4
                    + ((mi >> 3) + 2*(j >> 2));
            As[buf][idx] = f2tf32(vA[j]);
        }
    };
    auto storeB = [&](int buf) {
        if (BT) {
            const int nr = tid >> 1;
            const int nt = nr >> 3, ni = nr & 7;
            const int ks = (tid & 1);
            #pragma unroll
            for (int j = 0; j < 8; j++) {
                int idx = (((ks*16 + nt)*32) + ni*4 + (j & 3))*2 + (j >> 2);
                Bs[buf][idx] = f2tf32(vB[j]);
            }
        } else {
            const int kr = tid >> 4;
            const int ks = kr >> 3, ki = kr & 7;
            const int nt = tid & 15;
            #pragma unroll
            for (int j = 0; j < 8; j++) {
                int idx = (((ks*16 + nt)*32) + j*4 + (ki & 3))*2 + (ki >> 2);
                Bs[buf][idx] = f2tf32(vB[j]);
            }
        }
    };

    // ---------------- prologue: fill buffer 0 ----------------
    loadA(0); loadB(0);
    storeA(0); storeB(0);
    __syncthreads();

    int cur = 0;
    for (int k0 = 0; k0 < K; k0 += 16) {
        const bool has_next = (k0 + 16) < K;
        // 1) prefetch next tile into registers (overlaps with compute)
        if (has_next) { loadA(k0 + 16); loadB(k0 + 16); }

        // 2) compute on current buffer
        #pragma unroll
        for (int ks = 0; ks < 2; ks++) {
            uint32_t af[4][4];
            #pragma unroll
            for (int i = 0; i < 4; i++) {
                uint4 t = *reinterpret_cast<const uint4*>(
                    &As[cur][(((ks*8) + wm*4 + i)*32 + lane)*4]);
                af[i][0]=t.x; af[i][1]=t.y; af[i][2]=t.z; af[i][3]=t.w;
            }
            uint32_t bf[4][2];
            #pragma unroll
            for (int j = 0; j < 4; j++) {
                uint2 t = *reinterpret_cast<const uint2*>(
                    &Bs[cur][(((ks*16) + wn*4 + j)*32 + lane)*2]);
                bf[j][0]=t.x; bf[j][1]=t.y;
            }
            #pragma unroll
            for (int i = 0; i < 4; i++)
                #pragma unroll
                for (int j = 0; j < 4; j++) {
                    asm volatile(
                        "mma.sync.aligned.m16n8k8.row.col.f32.tf32.tf32.f32 "
                        "{%0,%1,%2,%3}, {%4,%5,%6,%7}, {%8,%9}, {%0,%1,%2,%3};\n"
                        : "+f"(acc[i][j][0]), "+f"(acc[i][j][1]),
                          "+f"(acc[i][j][2]), "+f"(acc[i][j][3])
                        : "r"(af[i][0]), "r"(af[i][1]), "r"(af[i][2]), "r"(af[i][3]),
                          "r"(bf[j][0]), "r"(bf[j][1]));
                }
        }

        // 3) commit prefetched tile to the other buffer
        if (has_next) { storeA(cur ^ 1); storeB(cur ^ 1); }
        __syncthreads();
        cur ^= 1;
    }

    // ---------------- epilogue ----------------
    const float g = (MODE == 3) ? gscale[0] : 0.f;
    const int group = lane >> 2, tg = lane & 3;

    #pragma unroll
    for (int i = 0; i < 4; i++) {
        const int rowB = m0 + wm*64 + i*16;
        #pragma unroll
        for (int j = 0; j < 4; j++) {
            const int colB = n0 + wn*32 + j*8 + tg*2;
            #pragma unroll
            for (int r = 0; r < 4; r++) {
                const int row = rowB + group + ((r >= 2) ? 8 : 0);
                const int col = colB + (r & 1);
                if (row >= M || col >= N) continue;
                float v = acc[i][j][r];
                if (MODE == 0) v *= alpha;
                if (MODE >= 1) v += bias[col];
                if (MODE == 1) v = gelu_exact(v);
                if (MODE == 3) {
                    const int b  = row / NTOK;
                    const int rr = row - b * NTOK;
                    const long off = ((long)b * NTOT + 1 + rr) * DIM + col;
                    C[off] = resid[off] + g * v;
                } else {
                    C[(long)blockIdx.z * cBS + (long)row * ldc + col] = v;
                }
            }
        }
    }
}

// =====================================================================
// SIMT fp32 GEMM (tiny text-branch GEMMs)
// =====================================================================
template<int MODE>
__launch_bounds__(256)
__global__ void gemm_kernel(const float* __restrict__ A, int lda,
                            const float* __restrict__ B, int ldb,
                            float* __restrict__ C, int ldc,
                            int M, int N, int K,
                            const float* __restrict__ bias)
{
    const int BM = 64, BN = 64, BK = 16;
    __shared__ float Ast[BK][BM + 4];
    __shared__ float Bst[BK][BN];

    const int tid = threadIdx.x;
    const int tx = tid & 15, ty = tid >> 4;
    const int m0 = blockIdx.y * BM, n0 = blockIdx.x * BN;

    float acc[4][4] = {};
    const int aRow = tid >> 2, aCol = (tid & 3) * 4;

    for (int k0 = 0; k0 < K; k0 += BK) {
        {
            float4 v = make_float4(0.f,0.f,0.f,0.f);
            int gr = m0 + aRow;
            if (gr < M) {
                int gc = k0 + aCol;
                if (gc + 3 < K) v = *reinterpret_cast<const float4*>(A + (long)gr*lda + gc);
                else {
                    v.x = (gc+0<K)?A[(long)gr*lda+gc+0]:0.f;
                    v.y = (gc+1<K)?A[(long)gr*lda+gc+1]:0.f;
                    v.z = (gc+2<K)?A[(long)gr*lda+gc+2]:0.f;
                    v.w = (gc+3<K)?A[(long)gr*lda+gc+3]:0.f;
                }
            }
            Ast[aCol+0][aRow]=v.x; Ast[aCol+1][aRow]=v.y;
            Ast[aCol+2][aRow]=v.z; Ast[aCol+3][aRow]=v.w;
        }
        {
            int br = tid >> 4, bc = (tid & 15) * 4;
            float4 v = make_float4(0.f,0.f,0.f,0.f);
            int gk = k0 + br, gn = n0 + bc;
            if (gk < K && gn + 3 < N)
                v = *reinterpret_cast<const float4*>(B + (long)gk*ldb + gn);
            else if (gk < K) {
                v.x = (gn+0<N)?B[(long)gk*ldb+gn+0]:0.f;
                v.y = (gn+1<N)?B[(long)gk*ldb+gn+1]:0.f;
                v.z = (gn+2<N)?B[(long)gk*ldb+gn+2]:0.f;
                v.w = (gn+3<N)?B[(long)gk*ldb+gn+3]:0.f;
            }
            *reinterpret_cast<float4*>(&Bst[br][bc]) = v;
        }
        __syncthreads();
        #pragma unroll
        for (int k = 0; k < BK; k++) {
            float4 av = *reinterpret_cast<const float4*>(&Ast[k][ty*4]);
            float4 bv = *reinterpret_cast<const float4*>(&Bst[k][tx*4]);
            acc[0][0]+=av.x*bv.x; acc[0][1]+=av.x*bv.y; acc[0][2]+=av.x*bv.z; acc[0][3]+=av.x*bv.w;
            acc[1][0]+=av.y*bv.x; acc[1][1]+=av.y*bv.y; acc[1][2]+=av.y*bv.z; acc[1][3]+=av.y*bv.w;
            acc[2][0]+=av.z*bv.x; acc[2][1]+=av.z*bv.y; acc[2][2]+=av.z*bv.z; acc[2][3]+=av.z*bv.w;
            acc[3][0]+=av.w*bv.x; acc[3][1]+=av.w*bv.y; acc[3][2]+=av.w*bv.z; acc[3][3]+=av.w*bv.w;
        }
        __syncthreads();
    }

    #pragma unroll
    for (int i = 0; i < 4; i++) {
        int m = m0 + ty*4 + i; if (m >= M) continue;
        #pragma unroll
        for (int j = 0; j < 4; j++) {
            int n = n0 + tx*4 + j; if (n >= N) continue;
            float v = acc[i][j] + bias[n];
            if (MODE == 1) v = gelu_exact(v);
            C[(long)m*ldc + n] = v;
        }
    }
}

// ---------------- softmax over rows of g_attn (one warp per row) -------------
__global__ void softmax_kernel(float* __restrict__ S)
{
    int warp = (blockIdx.x * blockDim.x + threadIdx.x) >> 5;
    int lane = threadIdx.x & 31;
    if (warp >= (int)(BQ * NTOK)) return;
    float* p = S + (long)warp * NTOK;

    float v[7];
    float mx = -3.0e38f;
    #pragma unroll
    for (int it = 0; it < 7; it++) {
        int j = lane + it * 32;
        v[it] = (j < NTOK) ? p[j] : -3.0e38f;
        mx = fmaxf(mx, v[it]);
    }
    #pragma unroll
    for (int o = 16; o; o >>= 1) mx = fmaxf(mx, __shfl_xor_sync(0xffffffffu, mx, o));

    float s = 0.f;
    #pragma unroll
    for (int it = 0; it < 7; it++) {
        int j = lane + it * 32;
        if (j < NTOK) { v[it] = expf(v[it] - mx); s += v[it]; } else v[it] = 0.f;
    }
    #pragma unroll
    for (int o = 16; o; o >>= 1) s += __shfl_xor_sync(0xffffffffu, s, o);
    float inv = 1.f / s;
    #pragma unroll
    for (int it = 0; it < 7; it++) {
        int j = lane + it * 32;
        if (j < NTOK) p[j] = v[it] * inv;
    }
}

// ---------------- layernorm rows of g_tq in place ----------------------------
__global__ void layernorm_kernel(float* __restrict__ X,
                                 const float* __restrict__ w,
                                 const float* __restrict__ b)
{
    int row = blockIdx.x;
    float* p = X + (long)row * DIM;
    float s = 0.f, sq = 0.f;
    for (int j = threadIdx.x; j < DIM; j += blockDim.x) {
        float x = p[j]; s += x; sq += x * x;
    }
    __shared__ float rs[32], rq[32];
    int lane = threadIdx.x & 31, wid = threadIdx.x >> 5;
    #pragma unroll
    for (int o = 16; o; o >>= 1) {
        s  += __shfl_xor_sync(0xffffffffu, s, o);
        sq += __shfl_xor_sync(0xffffffffu, sq, o);
    }
    if (lane == 0) { rs[wid] = s; rq[wid] = sq; }
    __syncthreads();
    int nw = blockDim.x >> 5;
    if (wid == 0) {
        float a = (lane < nw) ? rs[lane] : 0.f;
        float c = (lane < nw) ? rq[lane] : 0.f;
        #pragma unroll
        for (int o = 16; o; o >>= 1) {
            a += __shfl_xor_sync(0xffffffffu, a, o);
            c += __shfl_xor_sync(0xffffffffu, c, o);
        }
        if (lane == 0) { rs[0] = a; rq[0] = c; }
    }
    __syncthreads();
    float mu  = rs[0] / DIM;
    float var = rq[0] / DIM - mu * mu;
    float rstd = rsqrtf(var + 1e-5f);
    for (int j = threadIdx.x; j < DIM; j += blockDim.x)
        p[j] = (p[j] - mu) * rstd * w[j] + b[j];
}

// ----- gating: out_row *= (1 + gamma*sigmoid(dot(out_row, tq_b)))  (in place)
__global__ void mask_refine_kernel(float* __restrict__ out,
                                   const float* __restrict__ tq,
                                   const float* __restrict__ gamma)
{
    int warp = (blockIdx.x * blockDim.x + threadIdx.x) >> 5;
    int lane = threadIdx.x & 31;
    if (warp >= (int)TTOT) return;
    int b = warp / NTOK;
    int r = warp - b * NTOK;
    float* p = out + ((long)b * NTOT + 1 + r) * DIM;
    const float* t = tq + (long)b * DIM;
    float d = 0.f;
    for (int j = lane; j < DIM; j += 32) d += p[j] * t[j];
    #pragma unroll
    for (int o = 16; o; o >>= 1) d += __shfl_xor_sync(0xffffffffu, d, o);
    float m  = 1.f / (1.f + expf(-d));
    float sc = 1.f + gamma[0] * m;
    for (int j = lane; j < DIM; j += 32) p[j] *= sc;
}

// ---------------- cls passthrough --------------------------------------------
__global__ void copy_cls_kernel(const float* __restrict__ img, float* __restrict__ out)
{
    int b = blockIdx.x;
    long base = (long)b * NTOT * DIM;
    for (int j = threadIdx.x; j < DIM; j += blockDim.x)
        out[base + j] = img[base + j];
}

// =====================================================================
extern "C" void kernel_launch(void* const* d_in, const int* in_sizes, int n_in,
                              void* d_out, int out_size)
{
    const float* img       = (const float*)d_in[0];
    const float* text      = (const float*)d_in[1];
    const float* w1_msg    = (const float*)d_in[2];
    const float* b1_msg    = (const float*)d_in[3];
    const float* w2_msg    = (const float*)d_in[4];
    const float* b2_msg    = (const float*)d_in[5];
    const float* gamma_gcn = (const float*)d_in[6];
    const float* w1_txt    = (const float*)d_in[7];
    const float* b1_txt    = (const float*)d_in[8];
    const float* w2_txt    = (const float*)d_in[9];
    const float* b2_txt    = (const float*)d_in[10];
    const float* ln_w      = (const float*)d_in[11];
    const float* ln_b      = (const float*)d_in[12];
    const float* gamma     = (const float*)d_in[13];
    float* out = (float*)d_out;

    float *attn, *buf1, *buf2, *txt, *tq;
    cudaGetSymbolAddress((void**)&attn, g_attn);
    cudaGetSymbolAddress((void**)&buf1, g_buf1);
    cudaGetSymbolAddress((void**)&buf2, g_buf2);
    cudaGetSymbolAddress((void**)&txt,  g_txt);
    cudaGetSymbolAddress((void**)&tq,   g_tq);

    const float inv_sqrt_d = 0.03608439182435161f;  // 1/sqrt(768)
    const float* x = img + DIM;   // img[:,1:,:] view (batch stride NTOT*DIM)

    copy_cls_kernel<<<BQ, 256>>>(img, out);

    // 1) scores: S[b] = x x^T / sqrt(D)   (NT)
    mma_gemm<0, true><<<dim3(2, 2, BQ), 256>>>(
        x, (long)NTOT * DIM, DIM,
        x, (long)NTOT * DIM, DIM,
        attn, (long)NTOK * NTOK, NTOK,
        NTOK, NTOK, DIM, inv_sqrt_d, nullptr, nullptr, nullptr);

    // 2) softmax rows
    softmax_kernel<<<(TTOT * 32 + 255) / 256, 256>>>(attn);

    // 3) msg = A @ x  (NN, batched)
    mma_gemm<0, false><<<dim3(6, 2, BQ), 256>>>(
        attn, (long)NTOK * NTOK, NTOK,
        x, (long)NTOT * DIM, DIM,
        buf1, (long)NTOK * DIM, DIM,
        NTOK, DIM, NTOK, 1.f, nullptr, nullptr, nullptr);

    // 4) h = gelu(msg @ w1_msg + b1)
    mma_gemm<1, false><<<dim3(6, TTOT / 128, 1), 256>>>(
        buf1, 0, DIM, w1_msg, 0, DIM, buf2, 0, DIM,
        TTOT, DIM, DIM, 1.f, b1_msg, nullptr, nullptr);

    // 5) x_new = x + gamma_gcn*(h @ w2_msg + b2) -> d_out (remapped)
    mma_gemm<3, false><<<dim3(6, TTOT / 128, 1), 256>>>(
        buf2, 0, DIM, w2_msg, 0, DIM, out, 0, 0,
        TTOT, DIM, DIM, 1.f, b2_msg, img, gamma_gcn);

    // 6) text branch
    gemm_kernel<1><<<dim3(12, 4, 1), 256>>>(
        text, DTXT, w1_txt, DIM, txt, DIM, BQ, DIM, DTXT, b1_txt);
    gemm_kernel<2><<<dim3(12, 4, 1), 256>>>(
        txt, DIM, w2_txt, DIM, tq, DIM, BQ, DIM, DIM, b2_txt);
    layernorm_kernel<<<BQ, 256>>>(tq, ln_w, ln_b);

    // 9) gating epilogue in place on d_out token rows
    mask_refine_kernel<<<(TTOT * 32 + 255) / 256, 256>>>(out, tq, gamma);
}

// round 5
// speedup vs baseline: 2.0274x; 1.3302x over previous
#include <cuda_runtime.h>
#include <cstdint>

#define BQ   256
#define NTOK 196
#define NTOT 197
#define DIM  768
#define DTXT 512
#define TTOT (BQ*NTOK)

__device__ float g_attn[(size_t)BQ*NTOK*NTOK];
__device__ float g_buf1[(size_t)TTOT*DIM];
__device__ float g_buf2[(size_t)TTOT*DIM];
__device__ float g_txt [(size_t)BQ*DIM];
__device__ float g_tq  [(size_t)BQ*DIM];

__device__ __forceinline__ float gelu_exact(float x) { return x * normcdff(x); }
__device__ __forceinline__ uint32_t f2tf32(float x) {
    uint32_t r; asm("cvt.rna.tf32.f32 %0, %1;" : "=r"(r) : "f"(x)); return r;
}
// swizzled index into a [128 rows][16 k] u32 tile; bank-conflict-free for
// column-mode stores and all mma fragment reads; <=2-way for row-mode stores.
__device__ __forceinline__ int swz(int r, int k) {
    return r*16 + (k ^ (((r>>1)&3)<<2) ^ ((r>>3)&3));
}

// =====================================================================
// tf32 mma.sync GEMM, 128x128x16 tile, 8 warps, warp tile 64x32,
// double-buffered smem + register prefetch, swizzled row-major tiles.
//   BT=false: B is KxN (NN).  BT=true: B is NxK (NT).
// MODE 0: C=alpha*acc   MODE 1: C=gelu(acc+bias)
// MODE 3: out[remap]=resid[remap]+g*(acc+bias)
// =====================================================================
template<int MODE, bool BT>
__launch_bounds__(256, 2)
__global__ void mma_gemm(const float* __restrict__ A, long aBS, int lda,
                         const float* __restrict__ B, long bBS, int ldb,
                         float* __restrict__ C, long cBS, int ldc,
                         int M, int N, int K, float alpha,
                         const float* __restrict__ bias,
                         const float* __restrict__ resid,
                         const float* __restrict__ gscale)
{
    __shared__ uint32_t As[2][128*16];
    __shared__ uint32_t Bs[2][128*16];

    const int tid  = threadIdx.x;
    const int lane = tid & 31;
    const int wid  = tid >> 5;
    const int wm   = wid & 1;
    const int wn   = wid >> 1;
    const int m0   = blockIdx.y * 128;
    const int n0   = blockIdx.x * 128;

    const float* Ab = A + (long)blockIdx.z * aBS;
    const float* Bb = B + (long)blockIdx.z * bBS;

    float acc[4][4][4];
    #pragma unroll
    for (int i = 0; i < 4; i++)
        #pragma unroll
        for (int j = 0; j < 4; j++)
            #pragma unroll
            for (int r = 0; r < 4; r++) acc[i][j][r] = 0.f;

    // row-mode loader geometry (A always; B when BT)
    const int rw_r  = tid >> 1;          // row 0..127
    const int rw_kb = (tid & 1) * 8;     // k base 0/8
    // column-mode loader geometry (B when NN)
    const int cl_n  = tid & 127;
    const int cl_kh = (tid >> 7) * 8;

    float vA[8], vB[8];

    auto loadA = [&](int k0) {
        const int gm = m0 + rw_r, gk = k0 + rw_kb;
        if (gm < M && gk + 7 < K) {
            const float* p = Ab + (long)gm*lda + gk;
            float4 a = *reinterpret_cast<const float4*>(p);
            float4 b = *reinterpret_cast<const float4*>(p+4);
            vA[0]=a.x; vA[1]=a.y; vA[2]=a.z; vA[3]=a.w;
            vA[4]=b.x; vA[5]=b.y; vA[6]=b.z; vA[7]=b.w;
        } else {
            #pragma unroll
            for (int j = 0; j < 8; j++)
                vA[j] = (gm < M && gk+j < K) ? Ab[(long)gm*lda + gk+j] : 0.f;
        }
    };
    auto loadB = [&](int k0) {
        if (BT) {
            const int gn = n0 + rw_r, gk = k0 + rw_kb;
            if (gn < N && gk + 7 < K) {
                const float* p = Bb + (long)gn*ldb + gk;
                float4 a = *reinterpret_cast<const float4*>(p);
                float4 b = *reinterpret_cast<const float4*>(p+4);
                vB[0]=a.x; vB[1]=a.y; vB[2]=a.z; vB[3]=a.w;
                vB[4]=b.x; vB[5]=b.y; vB[6]=b.z; vB[7]=b.w;
            } else {
                #pragma unroll
                for (int j = 0; j < 8; j++)
                    vB[j] = (gn < N && gk+j < K) ? Bb[(long)gn*ldb + gk+j] : 0.f;
            }
        } else {
            const bool nok = (n0 + cl_n) < N;
            #pragma unroll
            for (int rr = 0; rr < 8; rr++) {
                const int gk = k0 + cl_kh + rr;
                vB[rr] = (nok && gk < K) ? Bb[(long)gk*ldb + n0 + cl_n] : 0.f;
            }
        }
    };
    auto storeA = [&](int buf) {
        #pragma unroll
        for (int j = 0; j < 8; j++)
            As[buf][swz(rw_r, rw_kb + j)] = f2tf32(vA[j]);
    };
    auto storeB = [&](int buf) {
        if (BT) {
            #pragma unroll
            for (int j = 0; j < 8; j++)
                Bs[buf][swz(rw_r, rw_kb + j)] = f2tf32(vB[j]);
        } else {
            #pragma unroll
            for (int rr = 0; rr < 8; rr++)
                Bs[buf][swz(cl_n, cl_kh + rr)] = f2tf32(vB[rr]);
        }
    };

    loadA(0); loadB(0);
    storeA(0); storeB(0);
    __syncthreads();

    const int g = lane >> 2, c = lane & 3;
    int cur = 0;
    for (int k0 = 0; k0 < K; k0 += 16) {
        const bool has_next = (k0 + 16) < K;
        if (has_next) { loadA(k0 + 16); loadB(k0 + 16); }

        #pragma unroll
        for (int ks = 0; ks < 2; ks++) {
            const int kb = ks * 8;
            uint32_t af[4][4];
            #pragma unroll
            for (int i = 0; i < 4; i++) {
                const int mb = wm*64 + i*16;
                af[i][0] = As[cur][swz(mb+g,   kb+c)];
                af[i][1] = As[cur][swz(mb+g+8, kb+c)];
                af[i][2] = As[cur][swz(mb+g,   kb+c+4)];
                af[i][3] = As[cur][swz(mb+g+8, kb+c+4)];
            }
            uint32_t bf[4][2];
            #pragma unroll
            for (int j = 0; j < 4; j++) {
                const int nb = wn*32 + j*8;
                bf[j][0] = Bs[cur][swz(nb+g, kb+c)];
                bf[j][1] = Bs[cur][swz(nb+g, kb+c+4)];
            }
            #pragma unroll
            for (int i = 0; i < 4; i++)
                #pragma unroll
                for (int j = 0; j < 4; j++) {
                    asm volatile(
                        "mma.sync.aligned.m16n8k8.row.col.f32.tf32.tf32.f32 "
                        "{%0,%1,%2,%3}, {%4,%5,%6,%7}, {%8,%9}, {%0,%1,%2,%3};\n"
                        : "+f"(acc[i][j][0]), "+f"(acc[i][j][1]),
                          "+f"(acc[i][j][2]), "+f"(acc[i][j][3])
                        : "r"(af[i][0]), "r"(af[i][1]), "r"(af[i][2]), "r"(af[i][3]),
                          "r"(bf[j][0]), "r"(bf[j][1]));
                }
        }

        if (has_next) { storeA(cur ^ 1); storeB(cur ^ 1); }
        __syncthreads();
        cur ^= 1;
    }

    const float gsc = (MODE == 3) ? gscale[0] : 0.f;
    const int tg = lane & 3;
    #pragma unroll
    for (int i = 0; i < 4; i++) {
        const int rowB = m0 + wm*64 + i*16;
        #pragma unroll
        for (int j = 0; j < 4; j++) {
            const int colB = n0 + wn*32 + j*8 + tg*2;
            #pragma unroll
            for (int r = 0; r < 4; r++) {
                const int row = rowB + g + ((r >= 2) ? 8 : 0);
                const int col = colB + (r & 1);
                if (row >= M || col >= N) continue;
                float v = acc[i][j][r];
                if (MODE == 0) v *= alpha;
                if (MODE >= 1) v += bias[col];
                if (MODE == 1) v = gelu_exact(v);
                if (MODE == 3) {
                    const int b  = row / NTOK;
                    const int rr = row - b * NTOK;
                    const long off = ((long)b * NTOT + 1 + rr) * DIM + col;
                    C[off] = resid[off] + gsc * v;
                } else {
                    C[(long)blockIdx.z * cBS + (long)row * ldc + col] = v;
                }
            }
        }
    }
}

// ---------------- SIMT fp32 GEMM (tiny text-branch) --------------------------
template<int MODE>
__launch_bounds__(256)
__global__ void gemm_kernel(const float* __restrict__ A, int lda,
                            const float* __restrict__ B, int ldb,
                            float* __restrict__ C, int ldc,
                            int M, int N, int K,
                            const float* __restrict__ bias)
{
    const int BM = 64, BN = 64, BK = 16;
    __shared__ float Ast[BK][BM + 4];
    __shared__ float Bst[BK][BN];
    const int tid = threadIdx.x;
    const int tx = tid & 15, ty = tid >> 4;
    const int m0 = blockIdx.y * BM, n0 = blockIdx.x * BN;
    float acc[4][4] = {};
    const int aRow = tid >> 2, aCol = (tid & 3) * 4;

    for (int k0 = 0; k0 < K; k0 += BK) {
        {
            float4 v = make_float4(0.f,0.f,0.f,0.f);
            int gr = m0 + aRow;
            if (gr < M) {
                int gc = k0 + aCol;
                if (gc + 3 < K) v = *reinterpret_cast<const float4*>(A + (long)gr*lda + gc);
                else {
                    v.x=(gc<K)?A[(long)gr*lda+gc]:0.f;   v.y=(gc+1<K)?A[(long)gr*lda+gc+1]:0.f;
                    v.z=(gc+2<K)?A[(long)gr*lda+gc+2]:0.f; v.w=(gc+3<K)?A[(long)gr*lda+gc+3]:0.f;
                }
            }
            Ast[aCol+0][aRow]=v.x; Ast[aCol+1][aRow]=v.y;
            Ast[aCol+2][aRow]=v.z; Ast[aCol+3][aRow]=v.w;
        }
        {
            int br = tid >> 4, bc = (tid & 15) * 4;
            float4 v = make_float4(0.f,0.f,0.f,0.f);
            int gk = k0 + br, gn = n0 + bc;
            if (gk < K && gn + 3 < N)
                v = *reinterpret_cast<const float4*>(B + (long)gk*ldb + gn);
            *reinterpret_cast<float4*>(&Bst[br][bc]) = v;
        }
        __syncthreads();
        #pragma unroll
        for (int k = 0; k < BK; k++) {
            float4 av = *reinterpret_cast<const float4*>(&Ast[k][ty*4]);
            float4 bv = *reinterpret_cast<const float4*>(&Bst[k][tx*4]);
            acc[0][0]+=av.x*bv.x; acc[0][1]+=av.x*bv.y; acc[0][2]+=av.x*bv.z; acc[0][3]+=av.x*bv.w;
            acc[1][0]+=av.y*bv.x; acc[1][1]+=av.y*bv.y; acc[1][2]+=av.y*bv.z; acc[1][3]+=av.y*bv.w;
            acc[2][0]+=av.z*bv.x; acc[2][1]+=av.z*bv.y; acc[2][2]+=av.z*bv.z; acc[2][3]+=av.z*bv.w;
            acc[3][0]+=av.w*bv.x; acc[3][1]+=av.w*bv.y; acc[3][2]+=av.w*bv.z; acc[3][3]+=av.w*bv.w;
        }
        __syncthreads();
    }
    #pragma unroll
    for (int i = 0; i < 4; i++) {
        int m = m0 + ty*4 + i; if (m >= M) continue;
        #pragma unroll
        for (int j = 0; j < 4; j++) {
            int n = n0 + tx*4 + j; if (n >= N) continue;
            float v = acc[i][j] + bias[n];
            if (MODE == 1) v = gelu_exact(v);
            C[(long)m*ldc + n] = v;
        }
    }
}

__global__ void softmax_kernel(float* __restrict__ S)
{
    int warp = (blockIdx.x * blockDim.x + threadIdx.x) >> 5;
    int lane = threadIdx.x & 31;
    if (warp >= (int)(BQ * NTOK)) return;
    float* p = S + (long)warp * NTOK;
    float v[7], mx = -3.0e38f;
    #pragma unroll
    for (int it = 0; it < 7; it++) {
        int j = lane + it*32;
        v[it] = (j < NTOK) ? p[j] : -3.0e38f;
        mx = fmaxf(mx, v[it]);
    }
    #pragma unroll
    for (int o = 16; o; o >>= 1) mx = fmaxf(mx, __shfl_xor_sync(0xffffffffu, mx, o));
    float s = 0.f;
    #pragma unroll
    for (int it = 0; it < 7; it++) {
        int j = lane + it*32;
        if (j < NTOK) { v[it] = expf(v[it]-mx); s += v[it]; } else v[it] = 0.f;
    }
    #pragma unroll
    for (int o = 16; o; o >>= 1) s += __shfl_xor_sync(0xffffffffu, s, o);
    float inv = 1.f / s;
    #pragma unroll
    for (int it = 0; it < 7; it++) {
        int j = lane + it*32;
        if (j < NTOK) p[j] = v[it]*inv;
    }
}

__global__ void layernorm_kernel(float* __restrict__ X,
                                 const float* __restrict__ w,
                                 const float* __restrict__ b)
{
    int row = blockIdx.x;
    float* p = X + (long)row * DIM;
    float s = 0.f, sq = 0.f;
    for (int j = threadIdx.x; j < DIM; j += blockDim.x) {
        float x = p[j]; s += x; sq += x*x;
    }
    __shared__ float rs[32], rq[32];
    int lane = threadIdx.x & 31, wd = threadIdx.x >> 5;
    #pragma unroll
    for (int o = 16; o; o >>= 1) {
        s  += __shfl_xor_sync(0xffffffffu, s, o);
        sq += __shfl_xor_sync(0xffffffffu, sq, o);
    }
    if (lane == 0) { rs[wd] = s; rq[wd] = sq; }
    __syncthreads();
    int nw = blockDim.x >> 5;
    if (wd == 0) {
        float a = (lane < nw) ? rs[lane] : 0.f;
        float cc = (lane < nw) ? rq[lane] : 0.f;
        #pragma unroll
        for (int o = 16; o; o >>= 1) {
            a  += __shfl_xor_sync(0xffffffffu, a, o);
            cc += __shfl_xor_sync(0xffffffffu, cc, o);
        }
        if (lane == 0) { rs[0] = a; rq[0] = cc; }
    }
    __syncthreads();
    float mu = rs[0] / DIM;
    float var = rq[0] / DIM - mu*mu;
    float rstd = rsqrtf(var + 1e-5f);
    for (int j = threadIdx.x; j < DIM; j += blockDim.x)
        p[j] = (p[j]-mu)*rstd*w[j] + b[j];
}

__global__ void mask_refine_kernel(float* __restrict__ out,
                                   const float* __restrict__ tq,
                                   const float* __restrict__ gamma)
{
    int warp = (blockIdx.x * blockDim.x + threadIdx.x) >> 5;
    int lane = threadIdx.x & 31;
    if (warp >= (int)TTOT) return;
    int b = warp / NTOK, r = warp - b*NTOK;
    float* p = out + ((long)b*NTOT + 1 + r)*DIM;
    const float* t = tq + (long)b*DIM;
    float d = 0.f;
    for (int j = lane; j < DIM; j += 32) d += p[j]*t[j];
    #pragma unroll
    for (int o = 16; o; o >>= 1) d += __shfl_xor_sync(0xffffffffu, d, o);
    float sc = 1.f + gamma[0] / (1.f + expf(-d));
    for (int j = lane; j < DIM; j += 32) p[j] *= sc;
}

__global__ void copy_cls_kernel(const float* __restrict__ img, float* __restrict__ out)
{
    long base = (long)blockIdx.x * NTOT * DIM;
    for (int j = threadIdx.x; j < DIM; j += blockDim.x)
        out[base + j] = img[base + j];
}

// =====================================================================
extern "C" void kernel_launch(void* const* d_in, const int* in_sizes, int n_in,
                              void* d_out, int out_size)
{
    const float* img       = (const float*)d_in[0];
    const float* text      = (const float*)d_in[1];
    const float* w1_msg    = (const float*)d_in[2];
    const float* b1_msg    = (const float*)d_in[3];
    const float* w2_msg    = (const float*)d_in[4];
    const float* b2_msg    = (const float*)d_in[5];
    const float* gamma_gcn = (const float*)d_in[6];
    const float* w1_txt    = (const float*)d_in[7];
    const float* b1_txt    = (const float*)d_in[8];
    const float* w2_txt    = (const float*)d_in[9];
    const float* b2_txt    = (const float*)d_in[10];
    const float* ln_w      = (const float*)d_in[11];
    const float* ln_b      = (const float*)d_in[12];
    const float* gamma     = (const float*)d_in[13];
    float* out = (float*)d_out;

    float *attn, *buf1, *buf2, *txt, *tq;
    cudaGetSymbolAddress((void**)&attn, g_attn);
    cudaGetSymbolAddress((void**)&buf1, g_buf1);
    cudaGetSymbolAddress((void**)&buf2, g_buf2);
    cudaGetSymbolAddress((void**)&txt,  g_txt);
    cudaGetSymbolAddress((void**)&tq,   g_tq);

    const float inv_sqrt_d = 0.03608439182435161f;
    const float* x = img + DIM;

    copy_cls_kernel<<<BQ, 256>>>(img, out);

    mma_gemm<0, true><<<dim3(2, 2, BQ), 256>>>(
        x, (long)NTOT*DIM, DIM, x, (long)NTOT*DIM, DIM,
        attn, (long)NTOK*NTOK, NTOK,
        NTOK, NTOK, DIM, inv_sqrt_d, nullptr, nullptr, nullptr);

    softmax_kernel<<<(TTOT*32 + 255)/256, 256>>>(attn);

    mma_gemm<0, false><<<dim3(6, 2, BQ), 256>>>(
        attn, (long)NTOK*NTOK, NTOK, x, (long)NTOT*DIM, DIM,
        buf1, (long)NTOK*DIM, DIM,
        NTOK, DIM, NTOK, 1.f, nullptr, nullptr, nullptr);

    mma_gemm<1, false><<<dim3(6, TTOT/128, 1), 256>>>(
        buf1, 0, DIM, w1_msg, 0, DIM, buf2, 0, DIM,
        TTOT, DIM, DIM, 1.f, b1_msg, nullptr, nullptr);

    mma_gemm<3, false><<<dim3(6, TTOT/128, 1), 256>>>(
        buf2, 0, DIM, w2_msg, 0, DIM, out, 0, 0,
        TTOT, DIM, DIM, 1.f, b2_msg, img, gamma_gcn);

    gemm_kernel<1><<<dim3(12, 4, 1), 256>>>(
        text, DTXT, w1_txt, DIM, txt, DIM, BQ, DIM, DTXT, b1_txt);
    gemm_kernel<2><<<dim3(12, 4, 1), 256>>>(
        txt, DIM, w2_txt, DIM, tq, DIM, BQ, DIM, DIM, b2_txt);
    layernorm_kernel<<<BQ, 256>>>(tq, ln_w, ln_b);

    mask_refine_kernel<<<(TTOT*32 + 255)/256, 256>>>(out, tq, gamma);
}